// round 5
// baseline (speedup 1.0000x reference)
#include <cuda_runtime.h>
#include <cuda_bf16.h>
#include <stdint.h>
#include <math.h>

#define BB    2048
#define REPRK 8192
#define SS    24
#define DD    8
#define SBH   384   // S*BINS

// ===================== PTX helpers (non-arch-specific) ======================
__device__ __forceinline__ uint32_t smem_u32(const void* p) {
    uint32_t a;
    asm("{ .reg .u64 t; cvta.to.shared.u64 t, %1; cvt.u32.u64 %0, t; }" : "=r"(a) : "l"(p));
    return a;
}
__device__ __forceinline__ void cp16(uint32_t saddr, const void* g) {
    asm volatile("cp.async.cg.shared.global [%0], [%1], 16;" :: "r"(saddr), "l"(g));
}
#define CPCOMMIT asm volatile("cp.async.commit_group;" ::: "memory")
#define CPWAIT1  asm volatile("cp.async.wait_group 1;" ::: "memory")
#define CPWAIT0  asm volatile("cp.async.wait_group 0;" ::: "memory")

__device__ __forceinline__ void ldsm4(uint32_t* r, uint32_t addr) {
    asm volatile("ldmatrix.sync.aligned.m8n8.x4.shared.b16 {%0,%1,%2,%3}, [%4];"
        : "=r"(r[0]), "=r"(r[1]), "=r"(r[2]), "=r"(r[3]) : "r"(addr));
}
__device__ __forceinline__ void mma_bf16(float* d, const uint32_t* a, uint32_t b0, uint32_t b1) {
    asm volatile("mma.sync.aligned.m16n8k16.row.col.f32.bf16.bf16.f32 "
        "{%0,%1,%2,%3}, {%4,%5,%6,%7}, {%8,%9}, {%0,%1,%2,%3};"
        : "+f"(d[0]), "+f"(d[1]), "+f"(d[2]), "+f"(d[3])
        : "r"(a[0]), "r"(a[1]), "r"(a[2]), "r"(a[3]), "r"(b0), "r"(b1));
}

// ===================== scratch (device globals) =============================
__device__ __nv_bfloat16 g_Ahi[(size_t)BB * REPRK];       // 32 MB
__device__ __nv_bfloat16 g_Alo[(size_t)BB * REPRK];
__device__ __nv_bfloat16 g_WrgbTh[(size_t)512 * REPRK];   // 8 MB
__device__ __nv_bfloat16 g_WrgbTl[(size_t)512 * REPRK];
__device__ float g_rgb_part[4 * BB * 512];                // 16 MB split-K partials
__device__ float g_rgb_pre[BB * 512];
__device__ __nv_bfloat16 g_xvh[BB * 512], g_xvl[BB * 512];
__device__ __nv_bfloat16 g_xqh[BB * 512], g_xql[BB * 512];
__device__ __nv_bfloat16 g_vW1Th[512 * 512], g_vW1Tl[512 * 512];
__device__ __nv_bfloat16 g_vW2Th[512 * 512], g_vW2Tl[512 * 512];
__device__ __nv_bfloat16 g_qW1Th[512 * 512], g_qW1Tl[512 * 512];
__device__ __nv_bfloat16 g_qW2Th[512 * 512], g_qW2Tl[512 * 512];
__device__ __nv_bfloat16 g_t1h[BB * 512], g_t1l[BB * 512];
__device__ float g_qbase[BB * 512];
__device__ float g_act[BB * SS * DD];
__device__ __nv_bfloat16 g_q1h[(size_t)BB * SS * 512];    // 50 MB  (s-major rows)
__device__ __nv_bfloat16 g_q1l[(size_t)BB * SS * 512];

// ===================== small helpers ========================================
__device__ __forceinline__ void split_bf16(float x, __nv_bfloat16& h, __nv_bfloat16& l) {
    h = __float2bfloat16_rn(x);
    l = __float2bfloat16_rn(x - __bfloat162float(h));
}
__device__ __forceinline__ float silu(float z) { return z / (1.f + expf(-z)); }

__device__ __forceinline__ float2 blockReduce2_256(float2 v) {
    __shared__ float2 sm[8];
    int lane = threadIdx.x & 31, w = threadIdx.x >> 5;
    #pragma unroll
    for (int o = 16; o > 0; o >>= 1) {
        v.x += __shfl_xor_sync(0xffffffffu, v.x, o);
        v.y += __shfl_xor_sync(0xffffffffu, v.y, o);
    }
    if (lane == 0) sm[w] = v;
    __syncthreads();
    if (threadIdx.x == 0) {
        float2 t = sm[0];
        #pragma unroll
        for (int i = 1; i < 8; i++) { t.x += sm[i].x; t.y += sm[i].y; }
        sm[0] = t;
    }
    __syncthreads();
    float2 r = sm[0];
    __syncthreads();
    return r;
}

// ===================== fused full-N (512) 3-pass bf16 layer =================
// C_pre = Ah*Bh^T + Ah*Bl^T + Al*Bh^T  (A[M][512], B[512][512] bf16, K=512)
// Tile MT x 512 (full N). 512 threads. EPI: 0=raw f32, 1=LN+SiLU->bf16 h/l,
// 2=LN+SiLU->qhead16 (s-major rows; out adv), 3=LN+SiLU->vhead1 (out value).
template<int WM, int EPI>
__global__ __launch_bounds__(512, 1)
void fused512(const __nv_bfloat16* __restrict__ Ah, const __nv_bfloat16* __restrict__ Al,
              const __nv_bfloat16* __restrict__ Bh, const __nv_bfloat16* __restrict__ Bl,
              float* __restrict__ Cout,
              __nv_bfloat16* __restrict__ Oh, __nv_bfloat16* __restrict__ Ol,
              const float* __restrict__ gw, const float* __restrict__ bw,
              const float* __restrict__ Whd, const float* __restrict__ bhd,
              float* __restrict__ hout) {
    constexpr int WN  = 16 / WM;          // warps along n
    constexpr int MT  = WM * 32;          // tile rows
    constexpr int NF  = 64 / WN;          // 8-col frags per warp
    constexpr int NF2 = NF / 2;
    constexpr uint32_t ABY   = (uint32_t)MT * 64;       // bytes per A(h or l) stage
    constexpr uint32_t STAGE = 2 * ABY + 65536;

    extern __shared__ char dsm[];
    __shared__ float2 lnp[512];
    __shared__ float hacc[MT * 16];

    const int tid = threadIdx.x, lane = tid & 31, wid = tid >> 5;
    const int wm = (WM == 1) ? 0 : (wid & (WM - 1));
    const int wn = wid / WM;
    const int m0 = blockIdx.x * MT;
    const uint32_t sb0 = smem_u32(dsm);

    // ---- loaders ----
    const int lrow = tid >> 2, lc = tid & 3;
    const uint32_t swz = (uint32_t)((lc ^ ((lrow >> 1) & 3)) * 16);
    const uint32_t sA = sb0 + lrow * 64 + swz;
    const uint32_t sB = sb0 + 2 * ABY + lrow * 64 + swz;
    const __nv_bfloat16* pAh = Ah + (size_t)(m0 + lrow) * 512 + lc * 8;
    const __nv_bfloat16* pAl = Al + (size_t)(m0 + lrow) * 512 + lc * 8;
    const __nv_bfloat16* pBh = Bh + (size_t)lrow * 512 + lc * 8;
    const __nv_bfloat16* pBl = Bl + (size_t)lrow * 512 + lc * 8;

#define FLOADST(s, ic) do { \
    uint32_t _so = (uint32_t)(s) * STAGE; \
    int _k = (ic) * 32; \
    if (lrow < MT) { cp16(sA + _so, pAh + _k); cp16(sA + _so + ABY, pAl + _k); } \
    _Pragma("unroll") \
    for (int _i = 0; _i < 4; _i++) { \
        cp16(sB + _so + _i * 8192u,          pBh + _i * 128 * 512 + _k); \
        cp16(sB + _so + _i * 8192u + 32768u, pBl + _i * 128 * 512 + _k); \
    } } while (0)

    FLOADST(0, 0); CPCOMMIT;
    FLOADST(1, 1); CPCOMMIT;

    float acc[2][NF][4];
    #pragma unroll
    for (int mf = 0; mf < 2; mf++)
        #pragma unroll
        for (int nf = 0; nf < NF; nf++)
            #pragma unroll
            for (int r = 0; r < 4; r++) acc[mf][nf][r] = 0.f;

    const int r15 = lane & 15, ksel = lane >> 4;

    for (int i = 0; i < 16; i++) {
        CPWAIT1;
        __syncthreads();
        uint32_t sbase = sb0 + (uint32_t)(i & 1) * STAGE;
        #pragma unroll
        for (int kt = 0; kt < 2; kt++) {
            const int cA = 2 * kt + ksel;
            uint32_t a[2][4], al[2][4];
            #pragma unroll
            for (int mf = 0; mf < 2; mf++) {
                int row = wm * 32 + mf * 16 + r15;
                uint32_t off = (uint32_t)(row * 64 + ((cA ^ ((row >> 1) & 3)) * 16));
                ldsm4(a[mf],  sbase + off);
                ldsm4(al[mf], sbase + ABY + off);
            }
            #pragma unroll
            for (int nf2 = 0; nf2 < NF2; nf2++) {
                int row = wn * (NF * 8) + nf2 * 16 + r15;
                uint32_t off = (uint32_t)(row * 64 + ((cA ^ ((row >> 1) & 3)) * 16));
                uint32_t bh[4], bl[4];
                ldsm4(bh, sbase + 2 * ABY + off);
                ldsm4(bl, sbase + 2 * ABY + 32768u + off);
                #pragma unroll
                for (int t = 0; t < 2; t++) {
                    int nf = nf2 * 2 + t;
                    #pragma unroll
                    for (int mf = 0; mf < 2; mf++) {
                        mma_bf16(acc[mf][nf], a[mf],  bh[t], bh[2 + t]);
                        mma_bf16(acc[mf][nf], a[mf],  bl[t], bl[2 + t]);
                        mma_bf16(acc[mf][nf], al[mf], bh[t], bh[2 + t]);
                    }
                }
            }
        }
        __syncthreads();
        if (i + 2 < 16) FLOADST(i & 1, i + 2);
        CPCOMMIT;
    }
#undef FLOADST
    CPWAIT0;
    __syncthreads();

    const int r8 = lane >> 2, cq = lane & 3;

    if (EPI == 0) {
        #pragma unroll
        for (int mf = 0; mf < 2; mf++)
            #pragma unroll
            for (int nf = 0; nf < NF; nf++) {
                int m = m0 + wm * 32 + mf * 16 + r8;
                int n = wn * (NF * 8) + nf * 8 + cq * 2;
                *(float2*)&Cout[(size_t)m * 512 + n] = make_float2(acc[mf][nf][0], acc[mf][nf][1]);
                *(float2*)&Cout[(size_t)(m + 8) * 512 + n] = make_float2(acc[mf][nf][2], acc[mf][nf][3]);
            }
        return;
    }

    // ---- LayerNorm over full row (512) ----
    float mus[2][2], invs[2][2];
    {
        #pragma unroll
        for (int mf = 0; mf < 2; mf++)
            #pragma unroll
            for (int hf = 0; hf < 2; hf++) {
                float s = 0.f, q = 0.f;
                #pragma unroll
                for (int nf = 0; nf < NF; nf++) {
                    float v0 = acc[mf][nf][hf * 2], v1 = acc[mf][nf][hf * 2 + 1];
                    s += v0 + v1; q += v0 * v0 + v1 * v1;
                }
                s += __shfl_xor_sync(0xffffffffu, s, 1);
                q += __shfl_xor_sync(0xffffffffu, q, 1);
                s += __shfl_xor_sync(0xffffffffu, s, 2);
                q += __shfl_xor_sync(0xffffffffu, q, 2);
                if (cq == 0) {
                    int rowt = wm * 32 + mf * 16 + r8 + hf * 8;
                    lnp[rowt * WN + wn] = make_float2(s, q);
                }
            }
        __syncthreads();
        #pragma unroll
        for (int mf = 0; mf < 2; mf++)
            #pragma unroll
            for (int hf = 0; hf < 2; hf++) {
                int rowt = wm * 32 + mf * 16 + r8 + hf * 8;
                float s = 0.f, q = 0.f;
                #pragma unroll
                for (int w = 0; w < WN; w++) {
                    float2 t = lnp[rowt * WN + w];
                    s += t.x; q += t.y;
                }
                float mu = s * (1.f / 512.f);
                mus[mf][hf] = mu;
                invs[mf][hf] = rsqrtf(q * (1.f / 512.f) - mu * mu + 1e-5f);
            }
    }

    // head prep (reuse dynamic smem for Wh slice)
    const int s16 = (EPI == 2) ? ((m0 >> 11) * 16) : 0;
    float* whs = (float*)dsm;
    if (EPI == 2) {
        #pragma unroll
        for (int j = 0; j < 4; j++)
            *(float4*)&whs[tid * 16 + j * 4] = *(const float4*)&Whd[(size_t)tid * SBH + s16 + j * 4];
        for (int idx = tid; idx < MT * 16; idx += 512) hacc[idx] = 0.f;
    }
    if (EPI == 3) {
        if (tid < 512) whs[tid] = Whd[tid];
        if (tid < MT) hacc[tid] = 0.f;
    }
    __syncthreads();

    #pragma unroll
    for (int mf = 0; mf < 2; mf++)
        #pragma unroll
        for (int hf = 0; hf < 2; hf++) {
            const int rowt = wm * 32 + mf * 16 + r8 + hf * 8;
            const float mu = mus[mf][hf], inv = invs[mf][hf];
            float ha[16];
            if (EPI == 2)
                #pragma unroll
                for (int c = 0; c < 16; c++) ha[c] = 0.f;
            float a1 = 0.f;
            #pragma unroll
            for (int nf = 0; nf < NF; nf++) {
                int colb = wn * (NF * 8) + nf * 8 + cq * 2;
                float2 gg = *(const float2*)&gw[colb];
                float2 be = *(const float2*)&bw[colb];
                float y0 = silu((acc[mf][nf][hf * 2]     - mu) * inv * gg.x + be.x);
                float y1 = silu((acc[mf][nf][hf * 2 + 1] - mu) * inv * gg.y + be.y);
                if (EPI == 1) {
                    __nv_bfloat16 h0, l0, h1, l1;
                    split_bf16(y0, h0, l0); split_bf16(y1, h1, l1);
                    __nv_bfloat162 ph; ph.x = h0; ph.y = h1;
                    __nv_bfloat162 pl; pl.x = l0; pl.y = l1;
                    size_t o = (size_t)(m0 + rowt) * 512 + colb;
                    *(__nv_bfloat162*)&Oh[o] = ph;
                    *(__nv_bfloat162*)&Ol[o] = pl;
                } else if (EPI == 2) {
                    const float4* w0 = (const float4*)&whs[colb * 16];
                    const float4* w1 = (const float4*)&whs[(colb + 1) * 16];
                    #pragma unroll
                    for (int j = 0; j < 4; j++) {
                        float4 a4 = w0[j], b4 = w1[j];
                        ha[j * 4 + 0] += y0 * a4.x + y1 * b4.x;
                        ha[j * 4 + 1] += y0 * a4.y + y1 * b4.y;
                        ha[j * 4 + 2] += y0 * a4.z + y1 * b4.z;
                        ha[j * 4 + 3] += y0 * a4.w + y1 * b4.w;
                    }
                } else {  // EPI 3
                    a1 += y0 * whs[colb] + y1 * whs[colb + 1];
                }
            }
            if (EPI == 2) {
                #pragma unroll
                for (int c = 0; c < 16; c++) {
                    ha[c] += __shfl_xor_sync(0xffffffffu, ha[c], 1);
                    ha[c] += __shfl_xor_sync(0xffffffffu, ha[c], 2);
                }
                if (cq == 0)
                    #pragma unroll
                    for (int c = 0; c < 16; c++) atomicAdd(&hacc[rowt * 16 + c], ha[c]);
            } else if (EPI == 3) {
                a1 += __shfl_xor_sync(0xffffffffu, a1, 1);
                a1 += __shfl_xor_sync(0xffffffffu, a1, 2);
                if (cq == 0) atomicAdd(&hacc[rowt], a1);
            }
        }

    if (EPI == 2) {
        __syncthreads();
        for (int idx = tid; idx < MT * 16; idx += 512) {
            int row = idx >> 4, c = idx & 15;
            int b = (m0 + row) & 2047;
            hout[(size_t)b * SBH + s16 + c] = hacc[idx] + bhd[s16 + c];
        }
    } else if (EPI == 3) {
        __syncthreads();
        if (tid < MT) hout[m0 + tid] = hacc[tid] + bhd[0];
    }
}

// ===================== HMMA 3-pass GEMM (rgb, 128x128 tile, split-K) =======
__global__ __launch_bounds__(512, 1)
void gemm_mma3(const __nv_bfloat16* __restrict__ Ah, const __nv_bfloat16* __restrict__ Al,
               const __nv_bfloat16* __restrict__ Bh, const __nv_bfloat16* __restrict__ Bl,
               float* __restrict__ C, int M, int N, int Kslice, int lda) {
    extern __shared__ char smdyn[];
    const int tid = threadIdx.x;
    const int lane = tid & 31, wid = tid >> 5;
    const int wm = wid & 3, wn = wid >> 2;
    const int m0 = blockIdx.y * 128, n0 = blockIdx.x * 128;
    const size_t kbase = (size_t)blockIdx.z * Kslice;
    float* Cz = C + (size_t)blockIdx.z * M * N;

    const int lrow = tid >> 2, lc = tid & 3;
    const int lpc = lc ^ ((lrow >> 1) & 3);
    const uint32_t sb0 = smem_u32(smdyn);
    const uint32_t s_store = sb0 + lrow * 64 + lpc * 16;
    const __nv_bfloat16* gAh = Ah + (size_t)(m0 + lrow) * lda + kbase + lc * 8;
    const __nv_bfloat16* gAl = Al + (size_t)(m0 + lrow) * lda + kbase + lc * 8;
    const __nv_bfloat16* gBh = Bh + (size_t)(n0 + lrow) * lda + kbase + lc * 8;
    const __nv_bfloat16* gBl = Bl + (size_t)(n0 + lrow) * lda + kbase + lc * 8;

    const int nch = Kslice >> 5;

#define LOADST(s, i) do { \
    uint32_t _so = s_store + (uint32_t)(s) * 32768u; \
    size_t _ko = (size_t)(i) * 32; \
    cp16(_so,          gAh + _ko); \
    cp16(_so +  8192,  gAl + _ko); \
    cp16(_so + 16384,  gBh + _ko); \
    cp16(_so + 24576,  gBl + _ko); } while (0)

    LOADST(0, 0); CPCOMMIT;
    LOADST(1, 1); CPCOMMIT;

    float acc[2][4][4];
    #pragma unroll
    for (int mf = 0; mf < 2; mf++)
        #pragma unroll
        for (int nf = 0; nf < 4; nf++)
            #pragma unroll
            for (int r = 0; r < 4; r++) acc[mf][nf][r] = 0.f;

    const int r15 = lane & 15, ksel = lane >> 4;

    for (int i = 0; i < nch; i++) {
        CPWAIT1;
        __syncthreads();
        uint32_t sb = sb0 + (uint32_t)(i & 1) * 32768u;
        #pragma unroll
        for (int kt = 0; kt < 2; kt++) {
            const int cA = 2 * kt + ksel;
            uint32_t a[2][4], al[2][4], bh[2][4], bl[2][4];
            #pragma unroll
            for (int mf = 0; mf < 2; mf++) {
                int row = wm * 32 + mf * 16 + r15;
                uint32_t off = (uint32_t)(row * 64 + ((cA ^ ((row >> 1) & 3)) * 16));
                ldsm4(a[mf], sb + off);
            }
            #pragma unroll
            for (int nf2 = 0; nf2 < 2; nf2++) {
                int row = wn * 32 + nf2 * 16 + r15;
                uint32_t off = (uint32_t)(row * 64 + ((cA ^ ((row >> 1) & 3)) * 16));
                ldsm4(bh[nf2], sb + 16384 + off);
                ldsm4(bl[nf2], sb + 24576 + off);
            }
            #pragma unroll
            for (int mf = 0; mf < 2; mf++)
                #pragma unroll
                for (int nf = 0; nf < 4; nf++) {
                    mma_bf16(acc[mf][nf], a[mf], bh[nf >> 1][nf & 1], bh[nf >> 1][2 + (nf & 1)]);
                    mma_bf16(acc[mf][nf], a[mf], bl[nf >> 1][nf & 1], bl[nf >> 1][2 + (nf & 1)]);
                }
            #pragma unroll
            for (int mf = 0; mf < 2; mf++) {
                int row = wm * 32 + mf * 16 + r15;
                uint32_t off = (uint32_t)(row * 64 + ((cA ^ ((row >> 1) & 3)) * 16));
                ldsm4(al[mf], sb + 8192 + off);
            }
            #pragma unroll
            for (int mf = 0; mf < 2; mf++)
                #pragma unroll
                for (int nf = 0; nf < 4; nf++)
                    mma_bf16(acc[mf][nf], al[mf], bh[nf >> 1][nf & 1], bh[nf >> 1][2 + (nf & 1)]);
        }
        __syncthreads();
        if (i + 2 < nch) LOADST(i & 1, i + 2);
        CPCOMMIT;
    }
#undef LOADST

    #pragma unroll
    for (int mf = 0; mf < 2; mf++)
        #pragma unroll
        for (int nf = 0; nf < 4; nf++) {
            int m = m0 + wm * 32 + mf * 16 + (lane >> 2);
            int n = n0 + wn * 32 + nf * 8 + (lane & 3) * 2;
            *(float2*)&Cz[(size_t)m * N + n] = make_float2(acc[mf][nf][0], acc[mf][nf][1]);
            *(float2*)&Cz[(size_t)(m + 8) * N + n] = make_float2(acc[mf][nf][2], acc[mf][nf][3]);
        }
}

// ---------------- split-K reduce ---------------------------------------------
__global__ void reduce4(const float* __restrict__ p, float* __restrict__ o) {
    int i = blockIdx.x * 256 + threadIdx.x;
    const size_t n = (size_t)BB * 512;
    float4 a = ((const float4*)p)[i];
    float4 b = ((const float4*)(p + n))[i];
    float4 c = ((const float4*)(p + 2 * n))[i];
    float4 d = ((const float4*)(p + 3 * n))[i];
    ((float4*)o)[i] = make_float4(a.x + b.x + c.x + d.x, a.y + b.y + c.y + d.y,
                                  a.z + b.z + c.z + d.z, a.w + b.w + c.w + d.w);
}

// ===================== prep kernels =========================================
__global__ void split_f32(const float* __restrict__ x, __nv_bfloat16* __restrict__ h,
                          __nv_bfloat16* __restrict__ l, int n4) {
    int i = blockIdx.x * blockDim.x + threadIdx.x;
    if (i >= n4) return;
    float4 v = ((const float4*)x)[i];
    __nv_bfloat16 h0, l0, h1, l1, h2, l2, h3, l3;
    split_bf16(v.x, h0, l0); split_bf16(v.y, h1, l1);
    split_bf16(v.z, h2, l2); split_bf16(v.w, h3, l3);
    __nv_bfloat162 ph0; ph0.x = h0; ph0.y = h1;
    __nv_bfloat162 ph1; ph1.x = h2; ph1.y = h3;
    __nv_bfloat162 pl0; pl0.x = l0; pl0.y = l1;
    __nv_bfloat162 pl1; pl1.x = l2; pl1.y = l3;
    ((__nv_bfloat162*)h)[i * 2] = ph0; ((__nv_bfloat162*)h)[i * 2 + 1] = ph1;
    ((__nv_bfloat162*)l)[i * 2] = pl0; ((__nv_bfloat162*)l)[i * 2 + 1] = pl1;
}

__global__ void trans_split(const float* __restrict__ W, int K, int N,
                            __nv_bfloat16* __restrict__ Th, __nv_bfloat16* __restrict__ Tl) {
    __shared__ float t[32][33];
    int k0 = blockIdx.x * 32, n0 = blockIdx.y * 32;
    int tx = threadIdx.x, ty = threadIdx.y;
    #pragma unroll
    for (int i = 0; i < 4; i++)
        t[ty + i * 8][tx] = W[(size_t)(k0 + ty + i * 8) * N + n0 + tx];
    __syncthreads();
    #pragma unroll
    for (int i = 0; i < 4; i++) {
        float v = t[tx][ty + i * 8];
        __nv_bfloat16 h, l; split_bf16(v, h, l);
        size_t o = (size_t)(n0 + ty + i * 8) * K + k0 + tx;
        Th[o] = h; Tl[o] = l;
    }
}

__global__ void trans_split_rgb(const float* __restrict__ vW, const float* __restrict__ qW,
                                __nv_bfloat16* __restrict__ Th, __nv_bfloat16* __restrict__ Tl) {
    __shared__ float t[32][33];
    int k0 = blockIdx.x * 32, n0 = blockIdx.y * 32;
    int tx = threadIdx.x, ty = threadIdx.y;
    const float* src = (n0 < 256) ? vW : qW;
    int nb = (n0 < 256) ? n0 : (n0 - 256);
    #pragma unroll
    for (int i = 0; i < 4; i++)
        t[ty + i * 8][tx] = src[(size_t)(k0 + ty + i * 8) * 256 + nb + tx];
    __syncthreads();
    #pragma unroll
    for (int i = 0; i < 4; i++) {
        float v = t[tx][ty + i * 8];
        __nv_bfloat16 h, l; split_bf16(v, h, l);
        size_t o = (size_t)(n0 + ty + i * 8) * REPRK + k0 + tx;
        Th[o] = h; Tl[o] = l;
    }
}

// ===================== activation kernels ===================================
__global__ void ln_tanh_rgb(const float* __restrict__ pre,
                            const float* __restrict__ vg, const float* __restrict__ vb,
                            const float* __restrict__ qg, const float* __restrict__ qb,
                            __nv_bfloat16* __restrict__ xvh, __nv_bfloat16* __restrict__ xvl,
                            __nv_bfloat16* __restrict__ xqh, __nv_bfloat16* __restrict__ xql) {
    int b = blockIdx.x, hsel = blockIdx.y, j = threadIdx.x;
    float x = pre[(size_t)b * 512 + hsel * 256 + j];
    float2 r = blockReduce2_256(make_float2(x, x * x));
    float mu = r.x * (1.f / 256.f);
    float inv = rsqrtf(r.y * (1.f / 256.f) - mu * mu + 1e-5f);
    const float* g  = hsel ? qg : vg;
    const float* be = hsel ? qb : vb;
    float y = tanhf((x - mu) * inv * g[j] + be[j]);
    __nv_bfloat16 h, l; split_bf16(y, h, l);
    if (hsel) { xqh[(size_t)b * 512 + j] = h; xql[(size_t)b * 512 + j] = l; }
    else      { xvh[(size_t)b * 512 + j] = h; xvl[(size_t)b * 512 + j] = l; }
}

__global__ void low_kernel(const float* __restrict__ low,
                           const float* __restrict__ vW, const float* __restrict__ vg, const float* __restrict__ vb,
                           const float* __restrict__ qW, const float* __restrict__ qg, const float* __restrict__ qb,
                           __nv_bfloat16* __restrict__ xvh, __nv_bfloat16* __restrict__ xvl,
                           __nv_bfloat16* __restrict__ xqh, __nv_bfloat16* __restrict__ xql) {
    int b = blockIdx.x, j = threadIdx.x;
    __shared__ float lo[32];
    if (j < 32) lo[j] = low[b * 32 + j];
    __syncthreads();
    float sv = 0.f, sq = 0.f;
    #pragma unroll 8
    for (int k = 0; k < 32; k++) {
        float l = lo[k];
        sv += l * vW[k * 256 + j];
        sq += l * qW[k * 256 + j];
    }
    float2 rv = blockReduce2_256(make_float2(sv, sv * sv));
    float muv = rv.x * (1.f / 256.f);
    float iv  = rsqrtf(rv.y * (1.f / 256.f) - muv * muv + 1e-5f);
    float yv = tanhf((sv - muv) * iv * vg[j] + vb[j]);
    __nv_bfloat16 h, l; split_bf16(yv, h, l);
    xvh[(size_t)b * 512 + 256 + j] = h; xvl[(size_t)b * 512 + 256 + j] = l;
    float2 rq = blockReduce2_256(make_float2(sq, sq * sq));
    float muq = rq.x * (1.f / 256.f);
    float iq  = rsqrtf(rq.y * (1.f / 256.f) - muq * muq + 1e-5f);
    float yq = tanhf((sq - muq) * iq * qg[j] + qb[j]);
    split_bf16(yq, h, l);
    xqh[(size_t)b * 512 + 256 + j] = h; xql[(size_t)b * 512 + 256 + j] = l;
}

__global__ void act_kernel(const int* __restrict__ cat, float* __restrict__ act) {
    int b = blockIdx.x * blockDim.x + threadIdx.x;
    if (b >= BB) return;
    float mids[3][8];
    #pragma unroll
    for (int d = 0; d < 8; d++) {
        float lowv = -1.f, width = 2.f;
        #pragma unroll
        for (int l = 0; l < 3; l++) {
            float w = width * (1.f / 16.f);
            float c = (float)cat[(b * 3 + l) * 8 + d];
            float nl = lowv + c * w;
            mids[l][d] = nl + 0.5f * w;
            lowv = nl; width = w;
        }
    }
    #pragma unroll
    for (int k = 0; k < 24; k++) {
        int ls = k >> 3, ds = k & 7;
        #pragma unroll
        for (int d = 0; d < 8; d++) {
            int lvl = ls + (d < ds ? 1 : 0);
            act[((size_t)b * 24 + k) * 8 + d] = (lvl == 0) ? 0.f : mids[lvl - 1][d];
        }
    }
}

// q layer1 (s-major output): base + rank-8 action + LN + SiLU -> bf16 h/l
__global__ void q1_kernel(const float* __restrict__ qbase, const float* __restrict__ act,
                          const float* __restrict__ qW1, const float* __restrict__ g,
                          const float* __restrict__ be,
                          __nv_bfloat16* __restrict__ oh, __nv_bfloat16* __restrict__ ol) {
    size_t idx = blockIdx.x;              // s*2048 + b
    int b = (int)(idx & 2047), s = (int)(idx >> 11);
    int j = threadIdx.x;
    __shared__ float a[8];
    if (j < 8) a[j] = act[((size_t)b * 24 + s) * 8 + j];
    __syncthreads();
    float x0 = qbase[(size_t)b * 512 + j];
    float x1 = qbase[(size_t)b * 512 + 256 + j];
    #pragma unroll
    for (int d = 0; d < 8; d++) {
        float av = a[d];
        x0 += av * qW1[(size_t)(512 + d) * 512 + j];
        x1 += av * qW1[(size_t)(512 + d) * 512 + 256 + j];
    }
    float2 r = blockReduce2_256(make_float2(x0 + x1, x0 * x0 + x1 * x1));
    float mu = r.x * (1.f / 512.f);
    float inv = rsqrtf(r.y * (1.f / 512.f) - mu * mu + 1e-5f);
    float z0 = (x0 - mu) * inv * g[j] + be[j];
    float z1 = (x1 - mu) * inv * g[j + 256] + be[j + 256];
    float y0 = silu(z0), y1 = silu(z1);
    __nv_bfloat16 h, l;
    split_bf16(y0, h, l); oh[idx * 512 + j] = h;       ol[idx * 512 + j] = l;
    split_bf16(y1, h, l); oh[idx * 512 + 256 + j] = h; ol[idx * 512 + 256 + j] = l;
}

// ===================== launch ================================================
#define RGB_DSMEM 65536
#define F1_DSMEM  139264   // WM=1: 2*(2*2048+65536)
#define F2_DSMEM  147456   // WM=2: 2*(2*4096+65536)

extern "C" void kernel_launch(void* const* d_in, const int* in_sizes, int n_in,
                              void* d_out, int out_size) {
    const float* rgb_obs = (const float*)d_in[0];
    const float* low_obs = (const float*)d_in[1];
    const int*   category = (const int*)d_in[2];
    const float* v_W_rgb = (const float*)d_in[3];
    const float* v_g_rgb = (const float*)d_in[4];
    const float* v_b_rgb = (const float*)d_in[5];
    const float* v_W_low = (const float*)d_in[6];
    const float* v_g_low = (const float*)d_in[7];
    const float* v_b_low = (const float*)d_in[8];
    const float* v_W1 = (const float*)d_in[9];
    const float* v_g1 = (const float*)d_in[10];
    const float* v_b1 = (const float*)d_in[11];
    const float* v_W2 = (const float*)d_in[12];
    const float* v_g2 = (const float*)d_in[13];
    const float* v_b2 = (const float*)d_in[14];
    const float* v_Wh = (const float*)d_in[15];
    const float* v_bh = (const float*)d_in[16];
    const float* q_W_rgb = (const float*)d_in[17];
    const float* q_g_rgb = (const float*)d_in[18];
    const float* q_b_rgb = (const float*)d_in[19];
    const float* q_W_low = (const float*)d_in[20];
    const float* q_g_low = (const float*)d_in[21];
    const float* q_b_low = (const float*)d_in[22];
    const float* q_W1 = (const float*)d_in[23];
    const float* q_g1 = (const float*)d_in[24];
    const float* q_b1 = (const float*)d_in[25];
    const float* q_W2 = (const float*)d_in[26];
    const float* q_g2 = (const float*)d_in[27];
    const float* q_b2 = (const float*)d_in[28];
    const float* q_Wh = (const float*)d_in[29];
    const float* q_bh = (const float*)d_in[30];

    float* out_value = (float*)d_out;
    float* out_adv   = out_value + BB;

    cudaFuncSetAttribute(gemm_mma3, cudaFuncAttributeMaxDynamicSharedMemorySize, RGB_DSMEM);
    cudaFuncSetAttribute(fused512<1, 0>, cudaFuncAttributeMaxDynamicSharedMemorySize, F1_DSMEM);
    cudaFuncSetAttribute(fused512<1, 1>, cudaFuncAttributeMaxDynamicSharedMemorySize, F1_DSMEM);
    cudaFuncSetAttribute(fused512<1, 3>, cudaFuncAttributeMaxDynamicSharedMemorySize, F1_DSMEM);
    cudaFuncSetAttribute(fused512<2, 2>, cudaFuncAttributeMaxDynamicSharedMemorySize, F2_DSMEM);

    __nv_bfloat16 *Ahi, *Alo, *WrgbTh, *WrgbTl, *xvh, *xvl, *xqh, *xql;
    __nv_bfloat16 *vW1Th, *vW1Tl, *vW2Th, *vW2Tl, *qW1Th, *qW1Tl, *qW2Th, *qW2Tl;
    __nv_bfloat16 *t1h, *t1l, *q1h, *q1l;
    float *rgb_part, *rgb_pre, *qbase, *act;
    cudaGetSymbolAddress((void**)&Ahi, g_Ahi);       cudaGetSymbolAddress((void**)&Alo, g_Alo);
    cudaGetSymbolAddress((void**)&WrgbTh, g_WrgbTh); cudaGetSymbolAddress((void**)&WrgbTl, g_WrgbTl);
    cudaGetSymbolAddress((void**)&rgb_part, g_rgb_part);
    cudaGetSymbolAddress((void**)&rgb_pre, g_rgb_pre);
    cudaGetSymbolAddress((void**)&xvh, g_xvh); cudaGetSymbolAddress((void**)&xvl, g_xvl);
    cudaGetSymbolAddress((void**)&xqh, g_xqh); cudaGetSymbolAddress((void**)&xql, g_xql);
    cudaGetSymbolAddress((void**)&vW1Th, g_vW1Th); cudaGetSymbolAddress((void**)&vW1Tl, g_vW1Tl);
    cudaGetSymbolAddress((void**)&vW2Th, g_vW2Th); cudaGetSymbolAddress((void**)&vW2Tl, g_vW2Tl);
    cudaGetSymbolAddress((void**)&qW1Th, g_qW1Th); cudaGetSymbolAddress((void**)&qW1Tl, g_qW1Tl);
    cudaGetSymbolAddress((void**)&qW2Th, g_qW2Th); cudaGetSymbolAddress((void**)&qW2Tl, g_qW2Tl);
    cudaGetSymbolAddress((void**)&t1h, g_t1h); cudaGetSymbolAddress((void**)&t1l, g_t1l);
    cudaGetSymbolAddress((void**)&qbase, g_qbase);
    cudaGetSymbolAddress((void**)&act, g_act);
    cudaGetSymbolAddress((void**)&q1h, g_q1h); cudaGetSymbolAddress((void**)&q1l, g_q1l);

    // ---- prep ----
    split_f32<<<(BB * REPRK / 4 + 255) / 256, 256>>>(rgb_obs, Ahi, Alo, BB * REPRK / 4);
    trans_split_rgb<<<dim3(REPRK / 32, 512 / 32), dim3(32, 8)>>>(v_W_rgb, q_W_rgb, WrgbTh, WrgbTl);
    trans_split<<<dim3(16, 16), dim3(32, 8)>>>(v_W1, 512, 512, vW1Th, vW1Tl);
    trans_split<<<dim3(16, 16), dim3(32, 8)>>>(v_W2, 512, 512, vW2Th, vW2Tl);
    trans_split<<<dim3(16, 16), dim3(32, 8)>>>(q_W1, 512, 512, qW1Th, qW1Tl);
    trans_split<<<dim3(16, 16), dim3(32, 8)>>>(q_W2, 512, 512, qW2Th, qW2Tl);
    act_kernel<<<(BB + 127) / 128, 128>>>(category, act);

    // ---- shared rgb features: split-K=4 over K=8192 ----
    gemm_mma3<<<dim3(4, BB / 128, 4), 512, RGB_DSMEM>>>(Ahi, Alo, WrgbTh, WrgbTl,
                                                        rgb_part, BB, 512, 2048, REPRK);
    reduce4<<<(BB * 512 / 4) / 256, 256>>>(rgb_part, rgb_pre);
    ln_tanh_rgb<<<dim3(BB, 2), 256>>>(rgb_pre, v_g_rgb, v_b_rgb, q_g_rgb, q_b_rgb, xvh, xvl, xqh, xql);
    low_kernel<<<BB, 256>>>(low_obs, v_W_low, v_g_low, v_b_low, q_W_low, q_g_low, q_b_low,
                            xvh, xvl, xqh, xql);

    // ---- value path (fused LN/SiLU epilogues) ----
    fused512<1, 1><<<BB / 32, 512, F1_DSMEM>>>(xvh, xvl, vW1Th, vW1Tl,
        nullptr, t1h, t1l, v_g1, v_b1, nullptr, nullptr, nullptr);
    fused512<1, 3><<<BB / 32, 512, F1_DSMEM>>>(t1h, t1l, vW2Th, vW2Tl,
        nullptr, nullptr, nullptr, v_g2, v_b2, v_Wh, v_bh, out_value);

    // ---- q path ----
    fused512<1, 0><<<BB / 32, 512, F1_DSMEM>>>(xqh, xql, qW1Th, qW1Tl,
        qbase, nullptr, nullptr, nullptr, nullptr, nullptr, nullptr, nullptr);
    q1_kernel<<<BB * SS, 256>>>(qbase, act, q_W1, q_g1, q_b1, q1h, q1l);
    fused512<2, 2><<<(BB * SS) / 64, 512, F2_DSMEM>>>(q1h, q1l, qW2Th, qW2Tl,
        nullptr, nullptr, nullptr, q_g2, q_b2, q_Wh, q_bh, out_adv);
}

// round 7
// speedup vs baseline: 1.4266x; 1.4266x over previous
#include <cuda_runtime.h>
#include <cuda_bf16.h>
#include <stdint.h>
#include <math.h>

#define BB    2048
#define REPRK 8192
#define SS    24
#define DD    8
#define SBH   384   // S*BINS

// ===================== PTX helpers (non-arch-specific) ======================
__device__ __forceinline__ uint32_t smem_u32(const void* p) {
    uint32_t a;
    asm("{ .reg .u64 t; cvta.to.shared.u64 t, %1; cvt.u32.u64 %0, t; }" : "=r"(a) : "l"(p));
    return a;
}
__device__ __forceinline__ void cp16(uint32_t saddr, const void* g) {
    asm volatile("cp.async.cg.shared.global [%0], [%1], 16;" :: "r"(saddr), "l"(g));
}
#define CPCOMMIT asm volatile("cp.async.commit_group;" ::: "memory")
#define CPWAIT1  asm volatile("cp.async.wait_group 1;" ::: "memory")

__device__ __forceinline__ void ldsm4(uint32_t* r, uint32_t addr) {
    asm volatile("ldmatrix.sync.aligned.m8n8.x4.shared.b16 {%0,%1,%2,%3}, [%4];"
        : "=r"(r[0]), "=r"(r[1]), "=r"(r[2]), "=r"(r[3]) : "r"(addr));
}
__device__ __forceinline__ void mma_bf16(float* d, const uint32_t* a, uint32_t b0, uint32_t b1) {
    asm volatile("mma.sync.aligned.m16n8k16.row.col.f32.bf16.bf16.f32 "
        "{%0,%1,%2,%3}, {%4,%5,%6,%7}, {%8,%9}, {%0,%1,%2,%3};"
        : "+f"(d[0]), "+f"(d[1]), "+f"(d[2]), "+f"(d[3])
        : "r"(a[0]), "r"(a[1]), "r"(a[2]), "r"(a[3]), "r"(b0), "r"(b1));
}

// ===================== scratch (device globals) =============================
__device__ __nv_bfloat16 g_Ahi[(size_t)BB * REPRK];       // 32 MB
__device__ __nv_bfloat16 g_Alo[(size_t)BB * REPRK];
__device__ __nv_bfloat16 g_WrgbTh[(size_t)512 * REPRK];   // 8 MB
__device__ __nv_bfloat16 g_WrgbTl[(size_t)512 * REPRK];
__device__ float g_rgb_part[4 * BB * 512];                // 16 MB split-K partials
__device__ __nv_bfloat16 g_xvh[BB * 512], g_xvl[BB * 512];
__device__ __nv_bfloat16 g_xqh[BB * 512], g_xql[BB * 512];
__device__ __nv_bfloat16 g_vW1Th[512 * 512], g_vW1Tl[512 * 512];
__device__ __nv_bfloat16 g_vW2Th[512 * 512], g_vW2Tl[512 * 512];
__device__ __nv_bfloat16 g_qW1Th[512 * 512], g_qW1Tl[512 * 512];
__device__ __nv_bfloat16 g_qW2Th[512 * 512], g_qW2Tl[512 * 512];
__device__ float g_t0[BB * 512];
__device__ __nv_bfloat16 g_t1h[BB * 512], g_t1l[BB * 512];
__device__ float g_t1f[BB * 512];
__device__ float g_qbase[BB * 512];
__device__ float g_act[BB * SS * DD];
__device__ __nv_bfloat16 g_q1h[(size_t)BB * SS * 512];    // 50 MB  (s-major rows)
__device__ __nv_bfloat16 g_q1l[(size_t)BB * SS * 512];
__device__ float g_q2pre[(size_t)BB * SS * 512];          // 100 MB (s-major rows)

// ===================== small helpers ========================================
__device__ __forceinline__ void split_bf16(float x, __nv_bfloat16& h, __nv_bfloat16& l) {
    h = __float2bfloat16_rn(x);
    l = __float2bfloat16_rn(x - __bfloat162float(h));
}
__device__ __forceinline__ float silu(float z) { return z / (1.f + expf(-z)); }

__device__ __forceinline__ float2 blockReduce2_256(float2 v) {
    __shared__ float2 sm[8];
    int lane = threadIdx.x & 31, w = threadIdx.x >> 5;
    #pragma unroll
    for (int o = 16; o > 0; o >>= 1) {
        v.x += __shfl_xor_sync(0xffffffffu, v.x, o);
        v.y += __shfl_xor_sync(0xffffffffu, v.y, o);
    }
    if (lane == 0) sm[w] = v;
    __syncthreads();
    if (threadIdx.x == 0) {
        float2 t = sm[0];
        #pragma unroll
        for (int i = 1; i < 8; i++) { t.x += sm[i].x; t.y += sm[i].y; }
        sm[0] = t;
    }
    __syncthreads();
    float2 r = sm[0];
    __syncthreads();
    return r;
}

// ===================== HMMA 3-pass GEMM (128x128 tile, split-K) =============
__global__ __launch_bounds__(512, 1)
void gemm_mma3(const __nv_bfloat16* __restrict__ Ah, const __nv_bfloat16* __restrict__ Al,
               const __nv_bfloat16* __restrict__ Bh, const __nv_bfloat16* __restrict__ Bl,
               float* __restrict__ C, int M, int N, int Kslice, int lda) {
    extern __shared__ char smdyn[];
    const int tid = threadIdx.x;
    const int lane = tid & 31, wid = tid >> 5;
    const int wm = wid & 3, wn = wid >> 2;
    const int m0 = blockIdx.y * 128, n0 = blockIdx.x * 128;
    const size_t kbase = (size_t)blockIdx.z * Kslice;
    float* Cz = C + (size_t)blockIdx.z * M * N;

    const int lrow = tid >> 2, lc = tid & 3;
    const int lpc = lc ^ ((lrow >> 1) & 3);
    const uint32_t sb0 = smem_u32(smdyn);
    const uint32_t s_store = sb0 + lrow * 64 + lpc * 16;
    const __nv_bfloat16* gAh = Ah + (size_t)(m0 + lrow) * lda + kbase + lc * 8;
    const __nv_bfloat16* gAl = Al + (size_t)(m0 + lrow) * lda + kbase + lc * 8;
    const __nv_bfloat16* gBh = Bh + (size_t)(n0 + lrow) * lda + kbase + lc * 8;
    const __nv_bfloat16* gBl = Bl + (size_t)(n0 + lrow) * lda + kbase + lc * 8;

    const int nch = Kslice >> 5;

#define LOADST(s, i) do { \
    uint32_t _so = s_store + (uint32_t)(s) * 32768u; \
    size_t _ko = (size_t)(i) * 32; \
    cp16(_so,          gAh + _ko); \
    cp16(_so +  8192,  gAl + _ko); \
    cp16(_so + 16384,  gBh + _ko); \
    cp16(_so + 24576,  gBl + _ko); } while (0)

    LOADST(0, 0); CPCOMMIT;
    LOADST(1, 1); CPCOMMIT;

    float acc[2][4][4];
    #pragma unroll
    for (int mf = 0; mf < 2; mf++)
        #pragma unroll
        for (int nf = 0; nf < 4; nf++)
            #pragma unroll
            for (int r = 0; r < 4; r++) acc[mf][nf][r] = 0.f;

    const int r15 = lane & 15, ksel = lane >> 4;

    for (int i = 0; i < nch; i++) {
        CPWAIT1;
        __syncthreads();
        uint32_t sb = sb0 + (uint32_t)(i & 1) * 32768u;
        #pragma unroll
        for (int kt = 0; kt < 2; kt++) {
            const int cA = 2 * kt + ksel;
            uint32_t a[2][4], al[2][4], bh[2][4], bl[2][4];
            #pragma unroll
            for (int mf = 0; mf < 2; mf++) {
                int row = wm * 32 + mf * 16 + r15;
                uint32_t off = (uint32_t)(row * 64 + ((cA ^ ((row >> 1) & 3)) * 16));
                ldsm4(a[mf], sb + off);
            }
            #pragma unroll
            for (int nf2 = 0; nf2 < 2; nf2++) {
                int row = wn * 32 + nf2 * 16 + r15;
                uint32_t off = (uint32_t)(row * 64 + ((cA ^ ((row >> 1) & 3)) * 16));
                ldsm4(bh[nf2], sb + 16384 + off);
                ldsm4(bl[nf2], sb + 24576 + off);
            }
            #pragma unroll
            for (int mf = 0; mf < 2; mf++)
                #pragma unroll
                for (int nf = 0; nf < 4; nf++) {
                    mma_bf16(acc[mf][nf], a[mf], bh[nf >> 1][nf & 1], bh[nf >> 1][2 + (nf & 1)]);
                    mma_bf16(acc[mf][nf], a[mf], bl[nf >> 1][nf & 1], bl[nf >> 1][2 + (nf & 1)]);
                }
            #pragma unroll
            for (int mf = 0; mf < 2; mf++) {
                int row = wm * 32 + mf * 16 + r15;
                uint32_t off = (uint32_t)(row * 64 + ((cA ^ ((row >> 1) & 3)) * 16));
                ldsm4(al[mf], sb + 8192 + off);
            }
            #pragma unroll
            for (int mf = 0; mf < 2; mf++)
                #pragma unroll
                for (int nf = 0; nf < 4; nf++)
                    mma_bf16(acc[mf][nf], al[mf], bh[nf >> 1][nf & 1], bh[nf >> 1][2 + (nf & 1)]);
        }
        __syncthreads();
        if (i + 2 < nch) LOADST(i & 1, i + 2);
        CPCOMMIT;
    }
#undef LOADST

    #pragma unroll
    for (int mf = 0; mf < 2; mf++)
        #pragma unroll
        for (int nf = 0; nf < 4; nf++) {
            int m = m0 + wm * 32 + mf * 16 + (lane >> 2);
            int n = n0 + wn * 32 + nf * 8 + (lane & 3) * 2;
            *(float2*)&Cz[(size_t)m * N + n] = make_float2(acc[mf][nf][0], acc[mf][nf][1]);
            *(float2*)&Cz[(size_t)(m + 8) * N + n] = make_float2(acc[mf][nf][2], acc[mf][nf][3]);
        }
}

// ===================== prep kernels =========================================
__global__ void split_f32(const float* __restrict__ x, __nv_bfloat16* __restrict__ h,
                          __nv_bfloat16* __restrict__ l, int n4) {
    int i = blockIdx.x * blockDim.x + threadIdx.x;
    if (i >= n4) return;
    float4 v = ((const float4*)x)[i];
    __nv_bfloat16 h0, l0, h1, l1, h2, l2, h3, l3;
    split_bf16(v.x, h0, l0); split_bf16(v.y, h1, l1);
    split_bf16(v.z, h2, l2); split_bf16(v.w, h3, l3);
    __nv_bfloat162 ph0; ph0.x = h0; ph0.y = h1;
    __nv_bfloat162 ph1; ph1.x = h2; ph1.y = h3;
    __nv_bfloat162 pl0; pl0.x = l0; pl0.y = l1;
    __nv_bfloat162 pl1; pl1.x = l2; pl1.y = l3;
    ((__nv_bfloat162*)h)[i * 2] = ph0; ((__nv_bfloat162*)h)[i * 2 + 1] = ph1;
    ((__nv_bfloat162*)l)[i * 2] = pl0; ((__nv_bfloat162*)l)[i * 2 + 1] = pl1;
}

__global__ void trans_split(const float* __restrict__ W, int K, int N,
                            __nv_bfloat16* __restrict__ Th, __nv_bfloat16* __restrict__ Tl) {
    __shared__ float t[32][33];
    int k0 = blockIdx.x * 32, n0 = blockIdx.y * 32;
    int tx = threadIdx.x, ty = threadIdx.y;
    #pragma unroll
    for (int i = 0; i < 4; i++)
        t[ty + i * 8][tx] = W[(size_t)(k0 + ty + i * 8) * N + n0 + tx];
    __syncthreads();
    #pragma unroll
    for (int i = 0; i < 4; i++) {
        float v = t[tx][ty + i * 8];
        __nv_bfloat16 h, l; split_bf16(v, h, l);
        size_t o = (size_t)(n0 + ty + i * 8) * K + k0 + tx;
        Th[o] = h; Tl[o] = l;
    }
}

__global__ void trans_split_rgb(const float* __restrict__ vW, const float* __restrict__ qW,
                                __nv_bfloat16* __restrict__ Th, __nv_bfloat16* __restrict__ Tl) {
    __shared__ float t[32][33];
    int k0 = blockIdx.x * 32, n0 = blockIdx.y * 32;
    int tx = threadIdx.x, ty = threadIdx.y;
    const float* src = (n0 < 256) ? vW : qW;
    int nb = (n0 < 256) ? n0 : (n0 - 256);
    #pragma unroll
    for (int i = 0; i < 4; i++)
        t[ty + i * 8][tx] = src[(size_t)(k0 + ty + i * 8) * 256 + nb + tx];
    __syncthreads();
    #pragma unroll
    for (int i = 0; i < 4; i++) {
        float v = t[tx][ty + i * 8];
        __nv_bfloat16 h, l; split_bf16(v, h, l);
        size_t o = (size_t)(n0 + ty + i * 8) * REPRK + k0 + tx;
        Th[o] = h; Tl[o] = l;
    }
}

// ===================== activation kernels ===================================
// reads 4 split-K partials directly (reduce4 folded in)
__global__ void ln_tanh_rgb(const float* __restrict__ part,
                            const float* __restrict__ vg, const float* __restrict__ vb,
                            const float* __restrict__ qg, const float* __restrict__ qb,
                            __nv_bfloat16* __restrict__ xvh, __nv_bfloat16* __restrict__ xvl,
                            __nv_bfloat16* __restrict__ xqh, __nv_bfloat16* __restrict__ xql) {
    int b = blockIdx.x, hsel = blockIdx.y, j = threadIdx.x;
    const size_t np = (size_t)BB * 512;
    size_t off = (size_t)b * 512 + hsel * 256 + j;
    float x = part[off] + part[off + np] + part[off + 2 * np] + part[off + 3 * np];
    float2 r = blockReduce2_256(make_float2(x, x * x));
    float mu = r.x * (1.f / 256.f);
    float inv = rsqrtf(r.y * (1.f / 256.f) - mu * mu + 1e-5f);
    const float* g  = hsel ? qg : vg;
    const float* be = hsel ? qb : vb;
    float y = tanhf((x - mu) * inv * g[j] + be[j]);
    __nv_bfloat16 h, l; split_bf16(y, h, l);
    if (hsel) { xqh[(size_t)b * 512 + j] = h; xql[(size_t)b * 512 + j] = l; }
    else      { xvh[(size_t)b * 512 + j] = h; xvl[(size_t)b * 512 + j] = l; }
}

__global__ void low_kernel(const float* __restrict__ low,
                           const float* __restrict__ vW, const float* __restrict__ vg, const float* __restrict__ vb,
                           const float* __restrict__ qW, const float* __restrict__ qg, const float* __restrict__ qb,
                           __nv_bfloat16* __restrict__ xvh, __nv_bfloat16* __restrict__ xvl,
                           __nv_bfloat16* __restrict__ xqh, __nv_bfloat16* __restrict__ xql) {
    int b = blockIdx.x, j = threadIdx.x;
    __shared__ float lo[32];
    if (j < 32) lo[j] = low[b * 32 + j];
    __syncthreads();
    float sv = 0.f, sq = 0.f;
    #pragma unroll 8
    for (int k = 0; k < 32; k++) {
        float l = lo[k];
        sv += l * vW[k * 256 + j];
        sq += l * qW[k * 256 + j];
    }
    float2 rv = blockReduce2_256(make_float2(sv, sv * sv));
    float muv = rv.x * (1.f / 256.f);
    float iv  = rsqrtf(rv.y * (1.f / 256.f) - muv * muv + 1e-5f);
    float yv = tanhf((sv - muv) * iv * vg[j] + vb[j]);
    __nv_bfloat16 h, l; split_bf16(yv, h, l);
    xvh[(size_t)b * 512 + 256 + j] = h; xvl[(size_t)b * 512 + 256 + j] = l;
    float2 rq = blockReduce2_256(make_float2(sq, sq * sq));
    float muq = rq.x * (1.f / 256.f);
    float iq  = rsqrtf(rq.y * (1.f / 256.f) - muq * muq + 1e-5f);
    float yq = tanhf((sq - muq) * iq * qg[j] + qb[j]);
    split_bf16(yq, h, l);
    xqh[(size_t)b * 512 + 256 + j] = h; xql[(size_t)b * 512 + 256 + j] = l;
}

__global__ void act_kernel(const int* __restrict__ cat, float* __restrict__ act) {
    int b = blockIdx.x * blockDim.x + threadIdx.x;
    if (b >= BB) return;
    float mids[3][8];
    #pragma unroll
    for (int d = 0; d < 8; d++) {
        float lowv = -1.f, width = 2.f;
        #pragma unroll
        for (int l = 0; l < 3; l++) {
            float w = width * (1.f / 16.f);
            float c = (float)cat[(b * 3 + l) * 8 + d];
            float nl = lowv + c * w;
            mids[l][d] = nl + 0.5f * w;
            lowv = nl; width = w;
        }
    }
    #pragma unroll
    for (int k = 0; k < 24; k++) {
        int ls = k >> 3, ds = k & 7;
        #pragma unroll
        for (int d = 0; d < 8; d++) {
            int lvl = ls + (d < ds ? 1 : 0);
            act[((size_t)b * 24 + k) * 8 + d] = (lvl == 0) ? 0.f : mids[lvl - 1][d];
        }
    }
}

__global__ void ln_silu_512_split(const float* __restrict__ pre, const float* __restrict__ g,
                                  const float* __restrict__ be,
                                  __nv_bfloat16* __restrict__ oh, __nv_bfloat16* __restrict__ ol) {
    size_t row = blockIdx.x;
    int j = threadIdx.x;
    float x0 = pre[row * 512 + j];
    float x1 = pre[row * 512 + 256 + j];
    float2 r = blockReduce2_256(make_float2(x0 + x1, x0 * x0 + x1 * x1));
    float mu = r.x * (1.f / 512.f);
    float inv = rsqrtf(r.y * (1.f / 512.f) - mu * mu + 1e-5f);
    float z0 = (x0 - mu) * inv * g[j] + be[j];
    float z1 = (x1 - mu) * inv * g[j + 256] + be[j + 256];
    float y0 = silu(z0), y1 = silu(z1);
    __nv_bfloat16 h, l;
    split_bf16(y0, h, l); oh[row * 512 + j] = h;       ol[row * 512 + j] = l;
    split_bf16(y1, h, l); oh[row * 512 + 256 + j] = h; ol[row * 512 + 256 + j] = l;
}

__global__ void ln_silu_512_f32(const float* __restrict__ pre, const float* __restrict__ g,
                                const float* __restrict__ be, float* __restrict__ out) {
    size_t row = blockIdx.x;
    int j = threadIdx.x;
    float x0 = pre[row * 512 + j];
    float x1 = pre[row * 512 + 256 + j];
    float2 r = blockReduce2_256(make_float2(x0 + x1, x0 * x0 + x1 * x1));
    float mu = r.x * (1.f / 512.f);
    float inv = rsqrtf(r.y * (1.f / 512.f) - mu * mu + 1e-5f);
    float z0 = (x0 - mu) * inv * g[j] + be[j];
    float z1 = (x1 - mu) * inv * g[j + 256] + be[j + 256];
    out[row * 512 + j]       = silu(z0);
    out[row * 512 + 256 + j] = silu(z1);
}

// q layer1: one block per b, all 24 s-slots; action weights cached in smem.
// Output rows are s-major: row = s*2048 + b.
__global__ __launch_bounds__(256)
void q1_all(const float* __restrict__ qbase, const float* __restrict__ act,
            const float* __restrict__ qW1, const float* __restrict__ g,
            const float* __restrict__ be,
            __nv_bfloat16* __restrict__ oh, __nv_bfloat16* __restrict__ ol) {
    __shared__ float wact[8 * 512];   // 16 KB
    __shared__ float as[SS * DD];
    int b = blockIdx.x, j = threadIdx.x;
    for (int i = j; i < 8 * 512; i += 256)
        wact[i] = qW1[(size_t)(512 + (i >> 9)) * 512 + (i & 511)];
    for (int i = j; i < SS * DD; i += 256)
        as[i] = act[(size_t)b * SS * DD + i];
    float b0 = qbase[(size_t)b * 512 + j];
    float b1 = qbase[(size_t)b * 512 + 256 + j];
    float g0 = g[j], g1 = g[j + 256], e0 = be[j], e1 = be[j + 256];
    __syncthreads();
    for (int s = 0; s < SS; s++) {
        float x0 = b0, x1 = b1;
        #pragma unroll
        for (int d = 0; d < 8; d++) {
            float av = as[s * 8 + d];
            x0 += av * wact[d * 512 + j];
            x1 += av * wact[d * 512 + 256 + j];
        }
        float2 r = blockReduce2_256(make_float2(x0 + x1, x0 * x0 + x1 * x1));
        float mu = r.x * (1.f / 512.f);
        float inv = rsqrtf(r.y * (1.f / 512.f) - mu * mu + 1e-5f);
        float y0 = silu((x0 - mu) * inv * g0 + e0);
        float y1 = silu((x1 - mu) * inv * g1 + e1);
        size_t row = (size_t)s * BB + b;
        __nv_bfloat16 h, l;
        split_bf16(y0, h, l); oh[row * 512 + j] = h;       ol[row * 512 + j] = l;
        split_bf16(y1, h, l); oh[row * 512 + 256 + j] = h; ol[row * 512 + 256 + j] = l;
    }
}

__global__ void vhead(const float* __restrict__ v2, const float* __restrict__ Wh,
                      const float* __restrict__ bh, float* __restrict__ out) {
    int b = blockIdx.x, j = threadIdx.x;
    float s = v2[(size_t)b * 512 + j] * Wh[j] + v2[(size_t)b * 512 + 256 + j] * Wh[256 + j];
    float2 r = blockReduce2_256(make_float2(s, 0.f));
    if (j == 0) out[b] = r.x + bh[0];
}

// ---- fused LN + SiLU + diagonal q-head over q2pre (s-major rows) ----------
// grid 768 (64 rows each, same s), 256 threads, dynamic smem:
//   whs [512*16] f32 (32 KB) + ys [32*520] f32 (66.5 KB)
#define YSLD 520
__global__ __launch_bounds__(256)
void lnhead_q(const float* __restrict__ pre, const float* __restrict__ g,
              const float* __restrict__ be, const float* __restrict__ Wh,
              const float* __restrict__ bh, float* __restrict__ out) {
    extern __shared__ float sm[];
    float* whs = sm;             // [512][16]
    float* ys  = sm + 512 * 16;  // [32][YSLD]
    const int tid = threadIdx.x, lane = tid & 31, w = tid >> 5;
    const int r0 = blockIdx.x * 64;
    const int s16 = (r0 >> 11) * 16;

    for (int i = tid; i < 512 * 16; i += 256)
        whs[i] = Wh[(size_t)(i >> 4) * SBH + s16 + (i & 15)];
    __syncthreads();

    const int rowB = tid >> 3, c2 = tid & 7;
    const float2 bias = *(const float2*)&bh[s16 + c2 * 2];

    for (int chunk = 0; chunk < 2; chunk++) {
        int rbase = r0 + chunk * 32;
        // phase A: 8 warps x 4 rows — warp-level LN + SiLU into ys
        for (int rr = w; rr < 32; rr += 8) {
            const float* row = pre + (size_t)(rbase + rr) * 512;
            float v[16];
            float s1 = 0.f, s2 = 0.f;
            #pragma unroll
            for (int i = 0; i < 16; i++) {
                v[i] = row[lane + i * 32];
                s1 += v[i]; s2 += v[i] * v[i];
            }
            #pragma unroll
            for (int o = 16; o > 0; o >>= 1) {
                s1 += __shfl_xor_sync(0xffffffffu, s1, o);
                s2 += __shfl_xor_sync(0xffffffffu, s2, o);
            }
            float mu = s1 * (1.f / 512.f);
            float inv = rsqrtf(s2 * (1.f / 512.f) - mu * mu + 1e-5f);
            #pragma unroll
            for (int i = 0; i < 16; i++) {
                int col = lane + i * 32;
                ys[rr * YSLD + col] = silu((v[i] - mu) * inv * g[col] + be[col]);
            }
        }
        __syncthreads();
        // phase B: thread = (row, 2 head cols)
        float a0 = 0.f, a1 = 0.f;
        const float* yrow = ys + rowB * YSLD;
        #pragma unroll 8
        for (int k = 0; k < 512; k++) {
            float y = yrow[k];
            float2 w2 = *(const float2*)&whs[k * 16 + c2 * 2];
            a0 += y * w2.x; a1 += y * w2.y;
        }
        int brow = (rbase + rowB) & (BB - 1);
        *(float2*)&out[(size_t)brow * SBH + s16 + c2 * 2] =
            make_float2(a0 + bias.x, a1 + bias.y);
        __syncthreads();
    }
}

// ===================== launch ================================================
#define RGB_DSMEM 65536
#define LNHEAD_DSMEM ((512 * 16 + 32 * YSLD) * 4)

extern "C" void kernel_launch(void* const* d_in, const int* in_sizes, int n_in,
                              void* d_out, int out_size) {
    const float* rgb_obs = (const float*)d_in[0];
    const float* low_obs = (const float*)d_in[1];
    const int*   category = (const int*)d_in[2];
    const float* v_W_rgb = (const float*)d_in[3];
    const float* v_g_rgb = (const float*)d_in[4];
    const float* v_b_rgb = (const float*)d_in[5];
    const float* v_W_low = (const float*)d_in[6];
    const float* v_g_low = (const float*)d_in[7];
    const float* v_b_low = (const float*)d_in[8];
    const float* v_W1 = (const float*)d_in[9];
    const float* v_g1 = (const float*)d_in[10];
    const float* v_b1 = (const float*)d_in[11];
    const float* v_W2 = (const float*)d_in[12];
    const float* v_g2 = (const float*)d_in[13];
    const float* v_b2 = (const float*)d_in[14];
    const float* v_Wh = (const float*)d_in[15];
    const float* v_bh = (const float*)d_in[16];
    const float* q_W_rgb = (const float*)d_in[17];
    const float* q_g_rgb = (const float*)d_in[18];
    const float* q_b_rgb = (const float*)d_in[19];
    const float* q_W_low = (const float*)d_in[20];
    const float* q_g_low = (const float*)d_in[21];
    const float* q_b_low = (const float*)d_in[22];
    const float* q_W1 = (const float*)d_in[23];
    const float* q_g1 = (const float*)d_in[24];
    const float* q_b1 = (const float*)d_in[25];
    const float* q_W2 = (const float*)d_in[26];
    const float* q_g2 = (const float*)d_in[27];
    const float* q_b2 = (const float*)d_in[28];
    const float* q_Wh = (const float*)d_in[29];
    const float* q_bh = (const float*)d_in[30];

    float* out_value = (float*)d_out;
    float* out_adv   = out_value + BB;

    cudaFuncSetAttribute(gemm_mma3, cudaFuncAttributeMaxDynamicSharedMemorySize, RGB_DSMEM);
    cudaFuncSetAttribute(lnhead_q, cudaFuncAttributeMaxDynamicSharedMemorySize, LNHEAD_DSMEM);

    __nv_bfloat16 *Ahi, *Alo, *WrgbTh, *WrgbTl, *xvh, *xvl, *xqh, *xql;
    __nv_bfloat16 *vW1Th, *vW1Tl, *vW2Th, *vW2Tl, *qW1Th, *qW1Tl, *qW2Th, *qW2Tl;
    __nv_bfloat16 *t1h, *t1l, *q1h, *q1l;
    float *rgb_part, *t0, *t1f, *qbase, *act, *q2pre;
    cudaGetSymbolAddress((void**)&Ahi, g_Ahi);       cudaGetSymbolAddress((void**)&Alo, g_Alo);
    cudaGetSymbolAddress((void**)&WrgbTh, g_WrgbTh); cudaGetSymbolAddress((void**)&WrgbTl, g_WrgbTl);
    cudaGetSymbolAddress((void**)&rgb_part, g_rgb_part);
    cudaGetSymbolAddress((void**)&xvh, g_xvh); cudaGetSymbolAddress((void**)&xvl, g_xvl);
    cudaGetSymbolAddress((void**)&xqh, g_xqh); cudaGetSymbolAddress((void**)&xql, g_xql);
    cudaGetSymbolAddress((void**)&vW1Th, g_vW1Th); cudaGetSymbolAddress((void**)&vW1Tl, g_vW1Tl);
    cudaGetSymbolAddress((void**)&vW2Th, g_vW2Th); cudaGetSymbolAddress((void**)&vW2Tl, g_vW2Tl);
    cudaGetSymbolAddress((void**)&qW1Th, g_qW1Th); cudaGetSymbolAddress((void**)&qW1Tl, g_qW1Tl);
    cudaGetSymbolAddress((void**)&qW2Th, g_qW2Th); cudaGetSymbolAddress((void**)&qW2Tl, g_qW2Tl);
    cudaGetSymbolAddress((void**)&t0, g_t0);
    cudaGetSymbolAddress((void**)&t1h, g_t1h); cudaGetSymbolAddress((void**)&t1l, g_t1l);
    cudaGetSymbolAddress((void**)&t1f, g_t1f);
    cudaGetSymbolAddress((void**)&qbase, g_qbase);
    cudaGetSymbolAddress((void**)&act, g_act);
    cudaGetSymbolAddress((void**)&q1h, g_q1h); cudaGetSymbolAddress((void**)&q1l, g_q1l);
    cudaGetSymbolAddress((void**)&q2pre, g_q2pre);

    // ---- prep ----
    split_f32<<<(BB * REPRK / 4 + 255) / 256, 256>>>(rgb_obs, Ahi, Alo, BB * REPRK / 4);
    trans_split_rgb<<<dim3(REPRK / 32, 512 / 32), dim3(32, 8)>>>(v_W_rgb, q_W_rgb, WrgbTh, WrgbTl);
    trans_split<<<dim3(16, 16), dim3(32, 8)>>>(v_W1, 512, 512, vW1Th, vW1Tl);
    trans_split<<<dim3(16, 16), dim3(32, 8)>>>(v_W2, 512, 512, vW2Th, vW2Tl);
    trans_split<<<dim3(16, 16), dim3(32, 8)>>>(q_W1, 512, 512, qW1Th, qW1Tl);
    trans_split<<<dim3(16, 16), dim3(32, 8)>>>(q_W2, 512, 512, qW2Th, qW2Tl);
    act_kernel<<<(BB + 127) / 128, 128>>>(category, act);

    // ---- shared rgb features: split-K=4 over K=8192, reduce folded into LN ----
    gemm_mma3<<<dim3(4, BB / 128, 4), 512, RGB_DSMEM>>>(Ahi, Alo, WrgbTh, WrgbTl,
                                                        rgb_part, BB, 512, 2048, REPRK);
    ln_tanh_rgb<<<dim3(BB, 2), 256>>>(rgb_part, v_g_rgb, v_b_rgb, q_g_rgb, q_b_rgb,
                                      xvh, xvl, xqh, xql);
    low_kernel<<<BB, 256>>>(low_obs, v_W_low, v_g_low, v_b_low, q_W_low, q_g_low, q_b_low,
                            xvh, xvl, xqh, xql);

    // ---- value path ----
    gemm_mma3<<<dim3(4, BB / 128, 1), 512, RGB_DSMEM>>>(xvh, xvl, vW1Th, vW1Tl, t0, BB, 512, 512, 512);
    ln_silu_512_split<<<BB, 256>>>(t0, v_g1, v_b1, t1h, t1l);
    gemm_mma3<<<dim3(4, BB / 128, 1), 512, RGB_DSMEM>>>(t1h, t1l, vW2Th, vW2Tl, t0, BB, 512, 512, 512);
    ln_silu_512_f32<<<BB, 256>>>(t0, v_g2, v_b2, t1f);
    vhead<<<BB, 256>>>(t1f, v_Wh, v_bh, out_value);

    // ---- q path ----
    gemm_mma3<<<dim3(4, BB / 128, 1), 512, RGB_DSMEM>>>(xqh, xql, qW1Th, qW1Tl, qbase, BB, 512, 512, 512);
    q1_all<<<BB, 256>>>(qbase, act, q_W1, q_g1, q_b1, q1h, q1l);
    gemm_mma3<<<dim3(4, (BB * SS) / 128, 1), 512, RGB_DSMEM>>>(q1h, q1l, qW2Th, qW2Tl,
                                                               q2pre, BB * SS, 512, 512, 512);
    lnhead_q<<<(BB * SS) / 64, 256, LNHEAD_DSMEM>>>(q2pre, q_g2, q_b2, q_Wh, q_bh, out_adv);
}

// round 8
// speedup vs baseline: 1.4575x; 1.0217x over previous
#include <cuda_runtime.h>
#include <cuda_bf16.h>
#include <stdint.h>
#include <math.h>

#define BB    2048
#define REPRK 8192
#define SS    24
#define DD    8
#define SBH   384   // S*BINS

// ===================== PTX helpers (non-arch-specific) ======================
__device__ __forceinline__ uint32_t smem_u32(const void* p) {
    uint32_t a;
    asm("{ .reg .u64 t; cvta.to.shared.u64 t, %1; cvt.u32.u64 %0, t; }" : "=r"(a) : "l"(p));
    return a;
}
__device__ __forceinline__ void cp16(uint32_t saddr, const void* g) {
    asm volatile("cp.async.cg.shared.global [%0], [%1], 16;" :: "r"(saddr), "l"(g));
}
#define CPCOMMIT asm volatile("cp.async.commit_group;" ::: "memory")
#define CPWAIT1  asm volatile("cp.async.wait_group 1;" ::: "memory")

__device__ __forceinline__ void ldsm4(uint32_t* r, uint32_t addr) {
    asm volatile("ldmatrix.sync.aligned.m8n8.x4.shared.b16 {%0,%1,%2,%3}, [%4];"
        : "=r"(r[0]), "=r"(r[1]), "=r"(r[2]), "=r"(r[3]) : "r"(addr));
}
__device__ __forceinline__ void mma_bf16(float* d, const uint32_t* a, uint32_t b0, uint32_t b1) {
    asm volatile("mma.sync.aligned.m16n8k16.row.col.f32.bf16.bf16.f32 "
        "{%0,%1,%2,%3}, {%4,%5,%6,%7}, {%8,%9}, {%0,%1,%2,%3};"
        : "+f"(d[0]), "+f"(d[1]), "+f"(d[2]), "+f"(d[3])
        : "r"(a[0]), "r"(a[1]), "r"(a[2]), "r"(a[3]), "r"(b0), "r"(b1));
}

// ===================== scratch (device globals) =============================
__device__ __nv_bfloat16 g_Ahi[(size_t)BB * REPRK];       // 32 MB
__device__ __nv_bfloat16 g_Alo[(size_t)BB * REPRK];
__device__ __nv_bfloat16 g_WrgbTh[(size_t)512 * REPRK];   // 8 MB
__device__ __nv_bfloat16 g_WrgbTl[(size_t)512 * REPRK];
__device__ float g_rgb_part[4 * BB * 512];                // 16 MB: rgb splitk, then t0p/qbp
__device__ __nv_bfloat16 g_xvh[BB * 512], g_xvl[BB * 512];
__device__ __nv_bfloat16 g_xqh[BB * 512], g_xql[BB * 512];
__device__ __nv_bfloat16 g_vW1Th[512 * 512], g_vW1Tl[512 * 512];
__device__ __nv_bfloat16 g_vW2Th[512 * 512], g_vW2Tl[512 * 512];
__device__ __nv_bfloat16 g_qW1Th[512 * 512], g_qW1Tl[512 * 512];
__device__ __nv_bfloat16 g_qW2Th[512 * 512], g_qW2Tl[512 * 512];
__device__ __nv_bfloat16 g_t1h[BB * 512], g_t1l[BB * 512];
__device__ float g_act[BB * SS * DD];
__device__ __nv_bfloat16 g_q1h[(size_t)BB * SS * 512];    // 50 MB (s-major rows)
__device__ __nv_bfloat16 g_q1l[(size_t)BB * SS * 512];
__device__ float g_q2pre[(size_t)BB * SS * 512];          // 100 MB (s-major rows)

// ===================== small helpers ========================================
__device__ __forceinline__ void split_bf16(float x, __nv_bfloat16& h, __nv_bfloat16& l) {
    h = __float2bfloat16_rn(x);
    l = __float2bfloat16_rn(x - __bfloat162float(h));
}
__device__ __forceinline__ float silu(float z) { return z / (1.f + expf(-z)); }

__device__ __forceinline__ float2 blockReduce2_256(float2 v) {
    __shared__ float2 sm[8];
    int lane = threadIdx.x & 31, w = threadIdx.x >> 5;
    #pragma unroll
    for (int o = 16; o > 0; o >>= 1) {
        v.x += __shfl_xor_sync(0xffffffffu, v.x, o);
        v.y += __shfl_xor_sync(0xffffffffu, v.y, o);
    }
    if (lane == 0) sm[w] = v;
    __syncthreads();
    if (threadIdx.x == 0) {
        float2 t = sm[0];
        #pragma unroll
        for (int i = 1; i < 8; i++) { t.x += sm[i].x; t.y += sm[i].y; }
        sm[0] = t;
    }
    __syncthreads();
    float2 r = sm[0];
    __syncthreads();
    return r;
}

// ===================== HMMA 3-pass GEMM core (128x128 tile) =================
// C[m0..m0+128][n0..n0+128] (row-major, ld N) = 3-pass over K range
// [kbase, kbase + nch*32). A[*][lda], B[*][lda] bf16 row-major.
__device__ __forceinline__ void gemm_core(
    const __nv_bfloat16* __restrict__ Ah, const __nv_bfloat16* __restrict__ Al,
    const __nv_bfloat16* __restrict__ Bh, const __nv_bfloat16* __restrict__ Bl,
    float* __restrict__ C, int m0, int n0, int kbase, int lda, int N, int nch,
    char* smdyn) {
    const int tid = threadIdx.x;
    const int lane = tid & 31, wid = tid >> 5;
    const int wm = wid & 3, wn = wid >> 2;

    const int lrow = tid >> 2, lc = tid & 3;
    const int lpc = lc ^ ((lrow >> 1) & 3);
    const uint32_t sb0 = smem_u32(smdyn);
    const uint32_t s_store = sb0 + lrow * 64 + lpc * 16;
    const __nv_bfloat16* gAh = Ah + (size_t)(m0 + lrow) * lda + kbase + lc * 8;
    const __nv_bfloat16* gAl = Al + (size_t)(m0 + lrow) * lda + kbase + lc * 8;
    const __nv_bfloat16* gBh = Bh + (size_t)(n0 + lrow) * lda + kbase + lc * 8;
    const __nv_bfloat16* gBl = Bl + (size_t)(n0 + lrow) * lda + kbase + lc * 8;

#define LOADST(s, i) do { \
    uint32_t _so = s_store + (uint32_t)(s) * 32768u; \
    size_t _ko = (size_t)(i) * 32; \
    cp16(_so,          gAh + _ko); \
    cp16(_so +  8192,  gAl + _ko); \
    cp16(_so + 16384,  gBh + _ko); \
    cp16(_so + 24576,  gBl + _ko); } while (0)

    LOADST(0, 0); CPCOMMIT;
    LOADST(1, 1); CPCOMMIT;

    float acc[2][4][4];
    #pragma unroll
    for (int mf = 0; mf < 2; mf++)
        #pragma unroll
        for (int nf = 0; nf < 4; nf++)
            #pragma unroll
            for (int r = 0; r < 4; r++) acc[mf][nf][r] = 0.f;

    const int r15 = lane & 15, ksel = lane >> 4;

    for (int i = 0; i < nch; i++) {
        CPWAIT1;
        __syncthreads();
        uint32_t sb = sb0 + (uint32_t)(i & 1) * 32768u;
        #pragma unroll
        for (int kt = 0; kt < 2; kt++) {
            const int cA = 2 * kt + ksel;
            uint32_t a[2][4], al[2][4], bh[2][4], bl[2][4];
            #pragma unroll
            for (int mf = 0; mf < 2; mf++) {
                int row = wm * 32 + mf * 16 + r15;
                uint32_t off = (uint32_t)(row * 64 + ((cA ^ ((row >> 1) & 3)) * 16));
                ldsm4(a[mf], sb + off);
            }
            #pragma unroll
            for (int nf2 = 0; nf2 < 2; nf2++) {
                int row = wn * 32 + nf2 * 16 + r15;
                uint32_t off = (uint32_t)(row * 64 + ((cA ^ ((row >> 1) & 3)) * 16));
                ldsm4(bh[nf2], sb + 16384 + off);
                ldsm4(bl[nf2], sb + 24576 + off);
            }
            #pragma unroll
            for (int mf = 0; mf < 2; mf++)
                #pragma unroll
                for (int nf = 0; nf < 4; nf++) {
                    mma_bf16(acc[mf][nf], a[mf], bh[nf >> 1][nf & 1], bh[nf >> 1][2 + (nf & 1)]);
                    mma_bf16(acc[mf][nf], a[mf], bl[nf >> 1][nf & 1], bl[nf >> 1][2 + (nf & 1)]);
                }
            #pragma unroll
            for (int mf = 0; mf < 2; mf++) {
                int row = wm * 32 + mf * 16 + r15;
                uint32_t off = (uint32_t)(row * 64 + ((cA ^ ((row >> 1) & 3)) * 16));
                ldsm4(al[mf], sb + 8192 + off);
            }
            #pragma unroll
            for (int mf = 0; mf < 2; mf++)
                #pragma unroll
                for (int nf = 0; nf < 4; nf++)
                    mma_bf16(acc[mf][nf], al[mf], bh[nf >> 1][nf & 1], bh[nf >> 1][2 + (nf & 1)]);
        }
        __syncthreads();
        if (i + 2 < nch) LOADST(i & 1, i + 2);
        CPCOMMIT;
    }
#undef LOADST

    #pragma unroll
    for (int mf = 0; mf < 2; mf++)
        #pragma unroll
        for (int nf = 0; nf < 4; nf++) {
            int m = m0 + wm * 32 + mf * 16 + (lane >> 2);
            int n = n0 + wn * 32 + nf * 8 + (lane & 3) * 2;
            *(float2*)&C[(size_t)m * N + n] = make_float2(acc[mf][nf][0], acc[mf][nf][1]);
            *(float2*)&C[(size_t)(m + 8) * N + n] = make_float2(acc[mf][nf][2], acc[mf][nf][3]);
        }
}

// rgb GEMM: grid (4, 16, 4) splitk over K=8192
__global__ __launch_bounds__(512, 1)
void gemm_rgb(const __nv_bfloat16* __restrict__ Ah, const __nv_bfloat16* __restrict__ Al,
              const __nv_bfloat16* __restrict__ Bh, const __nv_bfloat16* __restrict__ Bl,
              float* __restrict__ C) {
    extern __shared__ char smdyn[];
    gemm_core(Ah, Al, Bh, Bl, C + (size_t)blockIdx.z * BB * 512,
              blockIdx.y * 128, blockIdx.x * 128, blockIdx.z * 2048, REPRK, 512, 64, smdyn);
}

// vW1 + qW1 packed, each splitk2. grid (4, 16, 4): z = job*2 + kz
__global__ __launch_bounds__(512, 1)
void gemm_dualA(const __nv_bfloat16* __restrict__ xvh, const __nv_bfloat16* __restrict__ xvl,
                const __nv_bfloat16* __restrict__ vBh, const __nv_bfloat16* __restrict__ vBl,
                const __nv_bfloat16* __restrict__ xqh, const __nv_bfloat16* __restrict__ xql,
                const __nv_bfloat16* __restrict__ qBh, const __nv_bfloat16* __restrict__ qBl,
                float* __restrict__ t0p, float* __restrict__ qbp) {
    extern __shared__ char smdyn[];
    int job = blockIdx.z >> 1, kz = blockIdx.z & 1;
    const __nv_bfloat16 *Ah = job ? xqh : xvh, *Al = job ? xql : xvl;
    const __nv_bfloat16 *Bh = job ? qBh : vBh, *Bl = job ? qBl : vBl;
    float* C = (job ? qbp : t0p) + (size_t)kz * BB * 512;
    gemm_core(Ah, Al, Bh, Bl, C, blockIdx.y * 128, blockIdx.x * 128, kz * 256, 512, 512, 8, smdyn);
}

// qW2 (full) + vW2 (splitk2) packed. grid (4, 416)
__global__ __launch_bounds__(512, 1)
void gemm_dualB(const __nv_bfloat16* __restrict__ q1h, const __nv_bfloat16* __restrict__ q1l,
                const __nv_bfloat16* __restrict__ qBh, const __nv_bfloat16* __restrict__ qBl,
                const __nv_bfloat16* __restrict__ t1h, const __nv_bfloat16* __restrict__ t1l,
                const __nv_bfloat16* __restrict__ vBh, const __nv_bfloat16* __restrict__ vBl,
                float* __restrict__ q2pre, float* __restrict__ t0p) {
    extern __shared__ char smdyn[];
    int y = blockIdx.y;
    if (y < 384) {
        gemm_core(q1h, q1l, qBh, qBl, q2pre, y * 128, blockIdx.x * 128, 0, 512, 512, 16, smdyn);
    } else {
        int j = y - 384, kz = j >> 4, y2 = j & 15;
        gemm_core(t1h, t1l, vBh, vBl, t0p + (size_t)kz * BB * 512,
                  y2 * 128, blockIdx.x * 128, kz * 256, 512, 512, 8, smdyn);
    }
}

// ===================== prep kernels =========================================
__global__ void split_f32(const float* __restrict__ x, __nv_bfloat16* __restrict__ h,
                          __nv_bfloat16* __restrict__ l, int n4) {
    int i = blockIdx.x * blockDim.x + threadIdx.x;
    if (i >= n4) return;
    float4 v = ((const float4*)x)[i];
    __nv_bfloat16 h0, l0, h1, l1, h2, l2, h3, l3;
    split_bf16(v.x, h0, l0); split_bf16(v.y, h1, l1);
    split_bf16(v.z, h2, l2); split_bf16(v.w, h3, l3);
    __nv_bfloat162 ph0; ph0.x = h0; ph0.y = h1;
    __nv_bfloat162 ph1; ph1.x = h2; ph1.y = h3;
    __nv_bfloat162 pl0; pl0.x = l0; pl0.y = l1;
    __nv_bfloat162 pl1; pl1.x = l2; pl1.y = l3;
    ((__nv_bfloat162*)h)[i * 2] = ph0; ((__nv_bfloat162*)h)[i * 2 + 1] = ph1;
    ((__nv_bfloat162*)l)[i * 2] = pl0; ((__nv_bfloat162*)l)[i * 2 + 1] = pl1;
}

// all four 512x512 weight transposes in one launch; z selects the job
__global__ void trans_split4(const float* __restrict__ W0, __nv_bfloat16* __restrict__ T0h, __nv_bfloat16* __restrict__ T0l,
                             const float* __restrict__ W1, __nv_bfloat16* __restrict__ T1h, __nv_bfloat16* __restrict__ T1l,
                             const float* __restrict__ W2, __nv_bfloat16* __restrict__ T2h, __nv_bfloat16* __restrict__ T2l,
                             const float* __restrict__ W3, __nv_bfloat16* __restrict__ T3h, __nv_bfloat16* __restrict__ T3l) {
    __shared__ float t[32][33];
    int z = blockIdx.z;
    const float* W = z == 0 ? W0 : z == 1 ? W1 : z == 2 ? W2 : W3;
    __nv_bfloat16* Th = z == 0 ? T0h : z == 1 ? T1h : z == 2 ? T2h : T3h;
    __nv_bfloat16* Tl = z == 0 ? T0l : z == 1 ? T1l : z == 2 ? T2l : T3l;
    int k0 = blockIdx.x * 32, n0 = blockIdx.y * 32;
    int tx = threadIdx.x, ty = threadIdx.y;
    #pragma unroll
    for (int i = 0; i < 4; i++)
        t[ty + i * 8][tx] = W[(size_t)(k0 + ty + i * 8) * 512 + n0 + tx];
    __syncthreads();
    #pragma unroll
    for (int i = 0; i < 4; i++) {
        float v = t[tx][ty + i * 8];
        __nv_bfloat16 h, l; split_bf16(v, h, l);
        size_t o = (size_t)(n0 + ty + i * 8) * 512 + k0 + tx;
        Th[o] = h; Tl[o] = l;
    }
}

__global__ void trans_split_rgb(const float* __restrict__ vW, const float* __restrict__ qW,
                                __nv_bfloat16* __restrict__ Th, __nv_bfloat16* __restrict__ Tl) {
    __shared__ float t[32][33];
    int k0 = blockIdx.x * 32, n0 = blockIdx.y * 32;
    int tx = threadIdx.x, ty = threadIdx.y;
    const float* src = (n0 < 256) ? vW : qW;
    int nb = (n0 < 256) ? n0 : (n0 - 256);
    #pragma unroll
    for (int i = 0; i < 4; i++)
        t[ty + i * 8][tx] = src[(size_t)(k0 + ty + i * 8) * 256 + nb + tx];
    __syncthreads();
    #pragma unroll
    for (int i = 0; i < 4; i++) {
        float v = t[tx][ty + i * 8];
        __nv_bfloat16 h, l; split_bf16(v, h, l);
        size_t o = (size_t)(n0 + ty + i * 8) * REPRK + k0 + tx;
        Th[o] = h; Tl[o] = l;
    }
}

// ===================== activation kernels ===================================
__global__ void ln_tanh_rgb(const float* __restrict__ part,
                            const float* __restrict__ vg, const float* __restrict__ vb,
                            const float* __restrict__ qg, const float* __restrict__ qb,
                            __nv_bfloat16* __restrict__ xvh, __nv_bfloat16* __restrict__ xvl,
                            __nv_bfloat16* __restrict__ xqh, __nv_bfloat16* __restrict__ xql) {
    int b = blockIdx.x, hsel = blockIdx.y, j = threadIdx.x;
    const size_t np = (size_t)BB * 512;
    size_t off = (size_t)b * 512 + hsel * 256 + j;
    float x = part[off] + part[off + np] + part[off + 2 * np] + part[off + 3 * np];
    float2 r = blockReduce2_256(make_float2(x, x * x));
    float mu = r.x * (1.f / 256.f);
    float inv = rsqrtf(r.y * (1.f / 256.f) - mu * mu + 1e-5f);
    const float* g  = hsel ? qg : vg;
    const float* be = hsel ? qb : vb;
    float y = tanhf((x - mu) * inv * g[j] + be[j]);
    __nv_bfloat16 h, l; split_bf16(y, h, l);
    if (hsel) { xqh[(size_t)b * 512 + j] = h; xql[(size_t)b * 512 + j] = l; }
    else      { xvh[(size_t)b * 512 + j] = h; xvl[(size_t)b * 512 + j] = l; }
}

__global__ void low_kernel(const float* __restrict__ low,
                           const float* __restrict__ vW, const float* __restrict__ vg, const float* __restrict__ vb,
                           const float* __restrict__ qW, const float* __restrict__ qg, const float* __restrict__ qb,
                           __nv_bfloat16* __restrict__ xvh, __nv_bfloat16* __restrict__ xvl,
                           __nv_bfloat16* __restrict__ xqh, __nv_bfloat16* __restrict__ xql) {
    int b = blockIdx.x, j = threadIdx.x;
    __shared__ float lo[32];
    if (j < 32) lo[j] = low[b * 32 + j];
    __syncthreads();
    float sv = 0.f, sq = 0.f;
    #pragma unroll 8
    for (int k = 0; k < 32; k++) {
        float l = lo[k];
        sv += l * vW[k * 256 + j];
        sq += l * qW[k * 256 + j];
    }
    float2 rv = blockReduce2_256(make_float2(sv, sv * sv));
    float muv = rv.x * (1.f / 256.f);
    float iv  = rsqrtf(rv.y * (1.f / 256.f) - muv * muv + 1e-5f);
    float yv = tanhf((sv - muv) * iv * vg[j] + vb[j]);
    __nv_bfloat16 h, l; split_bf16(yv, h, l);
    xvh[(size_t)b * 512 + 256 + j] = h; xvl[(size_t)b * 512 + 256 + j] = l;
    float2 rq = blockReduce2_256(make_float2(sq, sq * sq));
    float muq = rq.x * (1.f / 256.f);
    float iq  = rsqrtf(rq.y * (1.f / 256.f) - muq * muq + 1e-5f);
    float yq = tanhf((sq - muq) * iq * qg[j] + qb[j]);
    split_bf16(yq, h, l);
    xqh[(size_t)b * 512 + 256 + j] = h; xql[(size_t)b * 512 + 256 + j] = l;
}

__global__ void act_kernel(const int* __restrict__ cat, float* __restrict__ act) {
    int b = blockIdx.x * blockDim.x + threadIdx.x;
    if (b >= BB) return;
    float mids[3][8];
    #pragma unroll
    for (int d = 0; d < 8; d++) {
        float lowv = -1.f, width = 2.f;
        #pragma unroll
        for (int l = 0; l < 3; l++) {
            float w = width * (1.f / 16.f);
            float c = (float)cat[(b * 3 + l) * 8 + d];
            float nl = lowv + c * w;
            mids[l][d] = nl + 0.5f * w;
            lowv = nl; width = w;
        }
    }
    #pragma unroll
    for (int k = 0; k < 24; k++) {
        int ls = k >> 3, ds = k & 7;
        #pragma unroll
        for (int d = 0; d < 8; d++) {
            int lvl = ls + (d < ds ? 1 : 0);
            act[((size_t)b * 24 + k) * 8 + d] = (lvl == 0) ? 0.f : mids[lvl - 1][d];
        }
    }
}

// blocks [0,2048): q1_all (reads qbp partials); [2048,4096): ln_silu_split (t0p partials)
__global__ __launch_bounds__(256)
void mid_k(const float* __restrict__ qbp, const float* __restrict__ act,
           const float* __restrict__ qW1, const float* __restrict__ qg1, const float* __restrict__ qb1,
           const float* __restrict__ t0p, const float* __restrict__ vg1, const float* __restrict__ vb1,
           __nv_bfloat16* __restrict__ q1h, __nv_bfloat16* __restrict__ q1l,
           __nv_bfloat16* __restrict__ t1h, __nv_bfloat16* __restrict__ t1l) {
    const size_t np = (size_t)BB * 512;
    int j = threadIdx.x;
    if (blockIdx.x < BB) {
        // ---- q1_all ----
        __shared__ float wact[8 * 512];
        __shared__ float as[SS * DD];
        int b = blockIdx.x;
        for (int i = j; i < 8 * 512; i += 256)
            wact[i] = qW1[(size_t)(512 + (i >> 9)) * 512 + (i & 511)];
        for (int i = j; i < SS * DD; i += 256)
            as[i] = act[(size_t)b * SS * DD + i];
        float b0 = qbp[(size_t)b * 512 + j]       + qbp[np + (size_t)b * 512 + j];
        float b1 = qbp[(size_t)b * 512 + 256 + j] + qbp[np + (size_t)b * 512 + 256 + j];
        float g0 = qg1[j], g1 = qg1[j + 256], e0 = qb1[j], e1 = qb1[j + 256];
        __syncthreads();
        for (int s = 0; s < SS; s++) {
            float x0 = b0, x1 = b1;
            #pragma unroll
            for (int d = 0; d < 8; d++) {
                float av = as[s * 8 + d];
                x0 += av * wact[d * 512 + j];
                x1 += av * wact[d * 512 + 256 + j];
            }
            float2 r = blockReduce2_256(make_float2(x0 + x1, x0 * x0 + x1 * x1));
            float mu = r.x * (1.f / 512.f);
            float inv = rsqrtf(r.y * (1.f / 512.f) - mu * mu + 1e-5f);
            float y0 = silu((x0 - mu) * inv * g0 + e0);
            float y1 = silu((x1 - mu) * inv * g1 + e1);
            size_t row = (size_t)s * BB + b;
            __nv_bfloat16 h, l;
            split_bf16(y0, h, l); q1h[row * 512 + j] = h;       q1l[row * 512 + j] = l;
            split_bf16(y1, h, l); q1h[row * 512 + 256 + j] = h; q1l[row * 512 + 256 + j] = l;
        }
    } else {
        // ---- ln_silu_split for v path ----
        size_t row = blockIdx.x - BB;
        float x0 = t0p[row * 512 + j]       + t0p[np + row * 512 + j];
        float x1 = t0p[row * 512 + 256 + j] + t0p[np + row * 512 + 256 + j];
        float2 r = blockReduce2_256(make_float2(x0 + x1, x0 * x0 + x1 * x1));
        float mu = r.x * (1.f / 512.f);
        float inv = rsqrtf(r.y * (1.f / 512.f) - mu * mu + 1e-5f);
        float y0 = silu((x0 - mu) * inv * vg1[j] + vb1[j]);
        float y1 = silu((x1 - mu) * inv * vg1[j + 256] + vb1[j + 256]);
        __nv_bfloat16 h, l;
        split_bf16(y0, h, l); t1h[row * 512 + j] = h;       t1l[row * 512 + j] = l;
        split_bf16(y1, h, l); t1h[row * 512 + 256 + j] = h; t1l[row * 512 + 256 + j] = l;
    }
}

// vW2 partials -> LN -> SiLU -> value head, one block per b
__global__ __launch_bounds__(256)
void vfin(const float* __restrict__ t0p, const float* __restrict__ g,
          const float* __restrict__ be, const float* __restrict__ Wh,
          const float* __restrict__ bh, float* __restrict__ out) {
    const size_t np = (size_t)BB * 512;
    int b = blockIdx.x, j = threadIdx.x;
    float x0 = t0p[(size_t)b * 512 + j]       + t0p[np + (size_t)b * 512 + j];
    float x1 = t0p[(size_t)b * 512 + 256 + j] + t0p[np + (size_t)b * 512 + 256 + j];
    float2 r = blockReduce2_256(make_float2(x0 + x1, x0 * x0 + x1 * x1));
    float mu = r.x * (1.f / 512.f);
    float inv = rsqrtf(r.y * (1.f / 512.f) - mu * mu + 1e-5f);
    float y0 = silu((x0 - mu) * inv * g[j] + be[j]);
    float y1 = silu((x1 - mu) * inv * g[j + 256] + be[j + 256]);
    float s = y0 * Wh[j] + y1 * Wh[256 + j];
    float2 r2 = blockReduce2_256(make_float2(s, 0.f));
    if (j == 0) out[b] = r2.x + bh[0];
}

// ---- fused LN + SiLU + diagonal q-head over q2pre (s-major rows) ----------
// grid 768 (64 rows each, same s), 256 threads.
// dyn smem: whs [512*16] (32 KB) + ys [64*YSLD] (133 KB)
#define YSLD 520
__global__ __launch_bounds__(256)
void lnhead_q(const float* __restrict__ pre, const float* __restrict__ g,
              const float* __restrict__ be, const float* __restrict__ Wh,
              const float* __restrict__ bh, float* __restrict__ out) {
    extern __shared__ float sm[];
    float* whs = sm;             // [512][16]
    float* ys  = sm + 512 * 16;  // [64][YSLD]
    const int tid = threadIdx.x, lane = tid & 31, w = tid >> 5;
    const int r0 = blockIdx.x * 64;
    const int s16 = (r0 >> 11) * 16;

    for (int i = tid; i < 512 * 16; i += 256)
        whs[i] = Wh[(size_t)(i >> 4) * SBH + s16 + (i & 15)];

    // phase A: 8 warps x 8 rows — warp-level LN + SiLU into ys
    for (int rr = w; rr < 64; rr += 8) {
        const float* row = pre + (size_t)(r0 + rr) * 512;
        float v[16];
        float s1 = 0.f, s2 = 0.f;
        #pragma unroll
        for (int i = 0; i < 16; i++) {
            v[i] = row[lane + i * 32];
            s1 += v[i]; s2 += v[i] * v[i];
        }
        #pragma unroll
        for (int o = 16; o > 0; o >>= 1) {
            s1 += __shfl_xor_sync(0xffffffffu, s1, o);
            s2 += __shfl_xor_sync(0xffffffffu, s2, o);
        }
        float mu = s1 * (1.f / 512.f);
        float inv = rsqrtf(s2 * (1.f / 512.f) - mu * mu + 1e-5f);
        #pragma unroll
        for (int i = 0; i < 16; i++) {
            int col = lane + i * 32;
            ys[rr * YSLD + col] = silu((v[i] - mu) * inv * g[col] + be[col]);
        }
    }
    __syncthreads();

    // phase B: thread = (rid, 2 head cols) handling rows rid and rid+32
    const int rid = tid >> 3, c2 = tid & 7;
    const float2 bias = *(const float2*)&bh[s16 + c2 * 2];
    float a0 = 0.f, a1 = 0.f, c0 = 0.f, c1 = 0.f;
    const float* y0r = ys + rid * YSLD;
    const float* y1r = ys + (rid + 32) * YSLD;
    #pragma unroll 8
    for (int k = 0; k < 512; k++) {
        float2 w2 = *(const float2*)&whs[k * 16 + c2 * 2];
        float ya = y0r[k], yb = y1r[k];
        a0 += ya * w2.x; a1 += ya * w2.y;
        c0 += yb * w2.x; c1 += yb * w2.y;
    }
    int brow0 = (r0 + rid) & (BB - 1);
    int brow1 = (r0 + rid + 32) & (BB - 1);
    *(float2*)&out[(size_t)brow0 * SBH + s16 + c2 * 2] = make_float2(a0 + bias.x, a1 + bias.y);
    *(float2*)&out[(size_t)brow1 * SBH + s16 + c2 * 2] = make_float2(c0 + bias.x, c1 + bias.y);
}

// ===================== launch ================================================
#define GEMM_DSMEM 65536
#define LNHEAD_DSMEM ((512 * 16 + 64 * YSLD) * 4)

extern "C" void kernel_launch(void* const* d_in, const int* in_sizes, int n_in,
                              void* d_out, int out_size) {
    const float* rgb_obs = (const float*)d_in[0];
    const float* low_obs = (const float*)d_in[1];
    const int*   category = (const int*)d_in[2];
    const float* v_W_rgb = (const float*)d_in[3];
    const float* v_g_rgb = (const float*)d_in[4];
    const float* v_b_rgb = (const float*)d_in[5];
    const float* v_W_low = (const float*)d_in[6];
    const float* v_g_low = (const float*)d_in[7];
    const float* v_b_low = (const float*)d_in[8];
    const float* v_W1 = (const float*)d_in[9];
    const float* v_g1 = (const float*)d_in[10];
    const float* v_b1 = (const float*)d_in[11];
    const float* v_W2 = (const float*)d_in[12];
    const float* v_g2 = (const float*)d_in[13];
    const float* v_b2 = (const float*)d_in[14];
    const float* v_Wh = (const float*)d_in[15];
    const float* v_bh = (const float*)d_in[16];
    const float* q_W_rgb = (const float*)d_in[17];
    const float* q_g_rgb = (const float*)d_in[18];
    const float* q_b_rgb = (const float*)d_in[19];
    const float* q_W_low = (const float*)d_in[20];
    const float* q_g_low = (const float*)d_in[21];
    const float* q_b_low = (const float*)d_in[22];
    const float* q_W1 = (const float*)d_in[23];
    const float* q_g1 = (const float*)d_in[24];
    const float* q_b1 = (const float*)d_in[25];
    const float* q_W2 = (const float*)d_in[26];
    const float* q_g2 = (const float*)d_in[27];
    const float* q_b2 = (const float*)d_in[28];
    const float* q_Wh = (const float*)d_in[29];
    const float* q_bh = (const float*)d_in[30];

    float* out_value = (float*)d_out;
    float* out_adv   = out_value + BB;

    cudaFuncSetAttribute(gemm_rgb,   cudaFuncAttributeMaxDynamicSharedMemorySize, GEMM_DSMEM);
    cudaFuncSetAttribute(gemm_dualA, cudaFuncAttributeMaxDynamicSharedMemorySize, GEMM_DSMEM);
    cudaFuncSetAttribute(gemm_dualB, cudaFuncAttributeMaxDynamicSharedMemorySize, GEMM_DSMEM);
    cudaFuncSetAttribute(lnhead_q,   cudaFuncAttributeMaxDynamicSharedMemorySize, LNHEAD_DSMEM);

    __nv_bfloat16 *Ahi, *Alo, *WrgbTh, *WrgbTl, *xvh, *xvl, *xqh, *xql;
    __nv_bfloat16 *vW1Th, *vW1Tl, *vW2Th, *vW2Tl, *qW1Th, *qW1Tl, *qW2Th, *qW2Tl;
    __nv_bfloat16 *t1h, *t1l, *q1h, *q1l;
    float *rgb_part, *act, *q2pre;
    cudaGetSymbolAddress((void**)&Ahi, g_Ahi);       cudaGetSymbolAddress((void**)&Alo, g_Alo);
    cudaGetSymbolAddress((void**)&WrgbTh, g_WrgbTh); cudaGetSymbolAddress((void**)&WrgbTl, g_WrgbTl);
    cudaGetSymbolAddress((void**)&rgb_part, g_rgb_part);
    cudaGetSymbolAddress((void**)&xvh, g_xvh); cudaGetSymbolAddress((void**)&xvl, g_xvl);
    cudaGetSymbolAddress((void**)&xqh, g_xqh); cudaGetSymbolAddress((void**)&xql, g_xql);
    cudaGetSymbolAddress((void**)&vW1Th, g_vW1Th); cudaGetSymbolAddress((void**)&vW1Tl, g_vW1Tl);
    cudaGetSymbolAddress((void**)&vW2Th, g_vW2Th); cudaGetSymbolAddress((void**)&vW2Tl, g_vW2Tl);
    cudaGetSymbolAddress((void**)&qW1Th, g_qW1Th); cudaGetSymbolAddress((void**)&qW1Tl, g_qW1Tl);
    cudaGetSymbolAddress((void**)&qW2Th, g_qW2Th); cudaGetSymbolAddress((void**)&qW2Tl, g_qW2Tl);
    cudaGetSymbolAddress((void**)&t1h, g_t1h); cudaGetSymbolAddress((void**)&t1l, g_t1l);
    cudaGetSymbolAddress((void**)&act, g_act);
    cudaGetSymbolAddress((void**)&q1h, g_q1h); cudaGetSymbolAddress((void**)&q1l, g_q1l);
    cudaGetSymbolAddress((void**)&q2pre, g_q2pre);

    // rgb_part slices double as split-K partial buffers later:
    float* t0p = rgb_part;                       // slices 0,1
    float* qbp = rgb_part + 2 * (size_t)BB * 512; // slices 2,3

    // ---- prep ----
    split_f32<<<(BB * REPRK / 4 + 255) / 256, 256>>>(rgb_obs, Ahi, Alo, BB * REPRK / 4);
    trans_split_rgb<<<dim3(REPRK / 32, 512 / 32), dim3(32, 8)>>>(v_W_rgb, q_W_rgb, WrgbTh, WrgbTl);
    trans_split4<<<dim3(16, 16, 4), dim3(32, 8)>>>(v_W1, vW1Th, vW1Tl, v_W2, vW2Th, vW2Tl,
                                                   q_W1, qW1Th, qW1Tl, q_W2, qW2Th, qW2Tl);
    act_kernel<<<(BB + 127) / 128, 128>>>(category, act);

    // ---- shared rgb features: split-K=4 over K=8192, reduce folded into LN ----
    gemm_rgb<<<dim3(4, BB / 128, 4), 512, GEMM_DSMEM>>>(Ahi, Alo, WrgbTh, WrgbTl, rgb_part);
    ln_tanh_rgb<<<dim3(BB, 2), 256>>>(rgb_part, v_g_rgb, v_b_rgb, q_g_rgb, q_b_rgb,
                                      xvh, xvl, xqh, xql);
    low_kernel<<<BB, 256>>>(low_obs, v_W_low, v_g_low, v_b_low, q_W_low, q_g_low, q_b_low,
                            xvh, xvl, xqh, xql);

    // ---- layer 1 (v + q packed, split-K=2 each) ----
    gemm_dualA<<<dim3(4, 16, 4), 512, GEMM_DSMEM>>>(xvh, xvl, vW1Th, vW1Tl,
                                                    xqh, xql, qW1Th, qW1Tl, t0p, qbp);
    // ---- q1 expansion + v ln_silu in one launch ----
    mid_k<<<2 * BB, 256>>>(qbp, act, q_W1, q_g1, q_b1, t0p, v_g1, v_b1,
                           q1h, q1l, t1h, t1l);

    // ---- layer 2: qW2 (big) + vW2 (splitk2) packed ----
    gemm_dualB<<<dim3(4, 416), 512, GEMM_DSMEM>>>(q1h, q1l, qW2Th, qW2Tl,
                                                  t1h, t1l, vW2Th, vW2Tl, q2pre, t0p);

    // ---- heads ----
    vfin<<<BB, 256>>>(t0p, v_g2, v_b2, v_Wh, v_bh, out_value);
    lnhead_q<<<(BB * SS) / 64, 256, LNHEAD_DSMEM>>>(q2pre, q_g2, q_b2, q_Wh, q_bh, out_adv);
}

// round 9
// speedup vs baseline: 1.5684x; 1.0761x over previous
#include <cuda_runtime.h>
#include <cuda_fp16.h>
#include <stdint.h>
#include <math.h>

#define BB    2048
#define REPRK 8192
#define SS    24
#define DD    8
#define SBH   384   // S*BINS

// ===================== PTX helpers (non-arch-specific) ======================
__device__ __forceinline__ uint32_t smem_u32(const void* p) {
    uint32_t a;
    asm("{ .reg .u64 t; cvta.to.shared.u64 t, %1; cvt.u32.u64 %0, t; }" : "=r"(a) : "l"(p));
    return a;
}
__device__ __forceinline__ void cp16(uint32_t saddr, const void* g) {
    asm volatile("cp.async.cg.shared.global [%0], [%1], 16;" :: "r"(saddr), "l"(g));
}
#define CPCOMMIT asm volatile("cp.async.commit_group;" ::: "memory")
#define CPWAIT1  asm volatile("cp.async.wait_group 1;" ::: "memory")

__device__ __forceinline__ void ldsm4(uint32_t* r, uint32_t addr) {
    asm volatile("ldmatrix.sync.aligned.m8n8.x4.shared.b16 {%0,%1,%2,%3}, [%4];"
        : "=r"(r[0]), "=r"(r[1]), "=r"(r[2]), "=r"(r[3]) : "r"(addr));
}
// fp16 inputs, f32 accumulator (main pass)
__device__ __forceinline__ void mma_f32acc(float* d, const uint32_t* a, uint32_t b0, uint32_t b1) {
    asm volatile("mma.sync.aligned.m16n8k16.row.col.f32.f16.f16.f32 "
        "{%0,%1,%2,%3}, {%4,%5,%6,%7}, {%8,%9}, {%0,%1,%2,%3};"
        : "+f"(d[0]), "+f"(d[1]), "+f"(d[2]), "+f"(d[3])
        : "r"(a[0]), "r"(a[1]), "r"(a[2]), "r"(a[3]), "r"(b0), "r"(b1));
}
// fp16 inputs, f16 accumulator (correction passes; 2 output regs = 4 halves)
__device__ __forceinline__ void mma_f16acc(uint32_t* d, const uint32_t* a, uint32_t b0, uint32_t b1) {
    asm volatile("mma.sync.aligned.m16n8k16.row.col.f16.f16.f16.f16 "
        "{%0,%1}, {%2,%3,%4,%5}, {%6,%7}, {%0,%1};"
        : "+r"(d[0]), "+r"(d[1])
        : "r"(a[0]), "r"(a[1]), "r"(a[2]), "r"(a[3]), "r"(b0), "r"(b1));
}

// ===================== scratch (device globals) =============================
__device__ __half g_Ahi[(size_t)BB * REPRK];       // 32 MB
__device__ __half g_Alo[(size_t)BB * REPRK];
__device__ __half g_WrgbTh[(size_t)512 * REPRK];   // 8 MB
__device__ __half g_WrgbTl[(size_t)512 * REPRK];
__device__ float g_rgb_part[4 * BB * 512];         // 16 MB: rgb splitk, then t0p/qbp
__device__ __half g_xvh[BB * 512], g_xvl[BB * 512];
__device__ __half g_xqh[BB * 512], g_xql[BB * 512];
__device__ __half g_vW1Th[512 * 512], g_vW1Tl[512 * 512];
__device__ __half g_vW2Th[512 * 512], g_vW2Tl[512 * 512];
__device__ __half g_qW1Th[512 * 512], g_qW1Tl[512 * 512];
__device__ __half g_qW2Th[512 * 512], g_qW2Tl[512 * 512];
__device__ __half g_t1h[BB * 512], g_t1l[BB * 512];
__device__ float g_act[BB * SS * DD];
__device__ __half g_q1h[(size_t)BB * SS * 512];    // 50 MB (s-major rows)
__device__ __half g_q1l[(size_t)BB * SS * 512];
__device__ float g_q2pre[(size_t)BB * SS * 512];   // 100 MB (s-major rows)

// ===================== small helpers ========================================
__device__ __forceinline__ void split_h(float x, __half& h, __half& l) {
    h = __float2half_rn(x);
    l = __float2half_rn(x - __half2float(h));
}
__device__ __forceinline__ float silu(float z) { return z / (1.f + expf(-z)); }

__device__ __forceinline__ float2 blockReduce2_256(float2 v) {
    __shared__ float2 sm[8];
    int lane = threadIdx.x & 31, w = threadIdx.x >> 5;
    #pragma unroll
    for (int o = 16; o > 0; o >>= 1) {
        v.x += __shfl_xor_sync(0xffffffffu, v.x, o);
        v.y += __shfl_xor_sync(0xffffffffu, v.y, o);
    }
    if (lane == 0) sm[w] = v;
    __syncthreads();
    if (threadIdx.x == 0) {
        float2 t = sm[0];
        #pragma unroll
        for (int i = 1; i < 8; i++) { t.x += sm[i].x; t.y += sm[i].y; }
        sm[0] = t;
    }
    __syncthreads();
    float2 r = sm[0];
    __syncthreads();
    return r;
}

// ===================== HMMA 3-pass GEMM core (128x128 tile) =================
// pass1 (f32 acc): Ah*Bh^T ; passes 2+3 (shared f16 acc): Ah*Bl^T + Al*Bh^T
__device__ __forceinline__ void gemm_core(
    const __half* __restrict__ Ah, const __half* __restrict__ Al,
    const __half* __restrict__ Bh, const __half* __restrict__ Bl,
    float* __restrict__ C, int m0, int n0, int kbase, int lda, int N, int nch,
    char* smdyn) {
    const int tid = threadIdx.x;
    const int lane = tid & 31, wid = tid >> 5;
    const int wm = wid & 3, wn = wid >> 2;

    const int lrow = tid >> 2, lc = tid & 3;
    const int lpc = lc ^ ((lrow >> 1) & 3);
    const uint32_t sb0 = smem_u32(smdyn);
    const uint32_t s_store = sb0 + lrow * 64 + lpc * 16;
    const __half* gAh = Ah + (size_t)(m0 + lrow) * lda + kbase + lc * 8;
    const __half* gAl = Al + (size_t)(m0 + lrow) * lda + kbase + lc * 8;
    const __half* gBh = Bh + (size_t)(n0 + lrow) * lda + kbase + lc * 8;
    const __half* gBl = Bl + (size_t)(n0 + lrow) * lda + kbase + lc * 8;

#define LOADST(s, i) do { \
    uint32_t _so = s_store + (uint32_t)(s) * 32768u; \
    size_t _ko = (size_t)(i) * 32; \
    cp16(_so,          gAh + _ko); \
    cp16(_so +  8192,  gAl + _ko); \
    cp16(_so + 16384,  gBh + _ko); \
    cp16(_so + 24576,  gBl + _ko); } while (0)

    LOADST(0, 0); CPCOMMIT;
    LOADST(1, 1); CPCOMMIT;

    float acc[2][4][4];
    uint32_t cor[2][4][2];
    #pragma unroll
    for (int mf = 0; mf < 2; mf++)
        #pragma unroll
        for (int nf = 0; nf < 4; nf++) {
            #pragma unroll
            for (int r = 0; r < 4; r++) acc[mf][nf][r] = 0.f;
            cor[mf][nf][0] = 0u; cor[mf][nf][1] = 0u;
        }

    const int r15 = lane & 15, ksel = lane >> 4;

    for (int i = 0; i < nch; i++) {
        CPWAIT1;
        __syncthreads();
        uint32_t sb = sb0 + (uint32_t)(i & 1) * 32768u;
        #pragma unroll
        for (int kt = 0; kt < 2; kt++) {
            const int cA = 2 * kt + ksel;
            uint32_t a[2][4], al[2][4], bh[2][4], bl[2][4];
            #pragma unroll
            for (int mf = 0; mf < 2; mf++) {
                int row = wm * 32 + mf * 16 + r15;
                uint32_t off = (uint32_t)(row * 64 + ((cA ^ ((row >> 1) & 3)) * 16));
                ldsm4(a[mf], sb + off);
            }
            #pragma unroll
            for (int nf2 = 0; nf2 < 2; nf2++) {
                int row = wn * 32 + nf2 * 16 + r15;
                uint32_t off = (uint32_t)(row * 64 + ((cA ^ ((row >> 1) & 3)) * 16));
                ldsm4(bh[nf2], sb + 16384 + off);
                ldsm4(bl[nf2], sb + 24576 + off);
            }
            // pass1: f32 acc Ah*Bh ; pass2: f16 acc Ah*Bl
            #pragma unroll
            for (int mf = 0; mf < 2; mf++)
                #pragma unroll
                for (int nf = 0; nf < 4; nf++) {
                    mma_f32acc(acc[mf][nf], a[mf], bh[nf >> 1][nf & 1], bh[nf >> 1][2 + (nf & 1)]);
                    mma_f16acc(cor[mf][nf], a[mf], bl[nf >> 1][nf & 1], bl[nf >> 1][2 + (nf & 1)]);
                }
            #pragma unroll
            for (int mf = 0; mf < 2; mf++) {
                int row = wm * 32 + mf * 16 + r15;
                uint32_t off = (uint32_t)(row * 64 + ((cA ^ ((row >> 1) & 3)) * 16));
                ldsm4(al[mf], sb + 8192 + off);
            }
            // pass3: f16 acc Al*Bh (same accumulator as pass2)
            #pragma unroll
            for (int mf = 0; mf < 2; mf++)
                #pragma unroll
                for (int nf = 0; nf < 4; nf++)
                    mma_f16acc(cor[mf][nf], al[mf], bh[nf >> 1][nf & 1], bh[nf >> 1][2 + (nf & 1)]);
        }
        __syncthreads();
        if (i + 2 < nch) LOADST(i & 1, i + 2);
        CPCOMMIT;
    }
#undef LOADST

    #pragma unroll
    for (int mf = 0; mf < 2; mf++)
        #pragma unroll
        for (int nf = 0; nf < 4; nf++) {
            int m = m0 + wm * 32 + mf * 16 + (lane >> 2);
            int n = n0 + wn * 32 + nf * 8 + (lane & 3) * 2;
            __half2 c01 = *(__half2*)&cor[mf][nf][0];
            __half2 c23 = *(__half2*)&cor[mf][nf][1];
            *(float2*)&C[(size_t)m * N + n] =
                make_float2(acc[mf][nf][0] + __low2float(c01), acc[mf][nf][1] + __high2float(c01));
            *(float2*)&C[(size_t)(m + 8) * N + n] =
                make_float2(acc[mf][nf][2] + __low2float(c23), acc[mf][nf][3] + __high2float(c23));
        }
}

// rgb GEMM: grid (4, 16, 4) splitk over K=8192
__global__ __launch_bounds__(512, 1)
void gemm_rgb(const __half* __restrict__ Ah, const __half* __restrict__ Al,
              const __half* __restrict__ Bh, const __half* __restrict__ Bl,
              float* __restrict__ C) {
    extern __shared__ char smdyn[];
    gemm_core(Ah, Al, Bh, Bl, C + (size_t)blockIdx.z * BB * 512,
              blockIdx.y * 128, blockIdx.x * 128, blockIdx.z * 2048, REPRK, 512, 64, smdyn);
}

// vW1 + qW1 packed, each splitk2. grid (4, 16, 4): z = job*2 + kz
__global__ __launch_bounds__(512, 1)
void gemm_dualA(const __half* __restrict__ xvh, const __half* __restrict__ xvl,
                const __half* __restrict__ vBh, const __half* __restrict__ vBl,
                const __half* __restrict__ xqh, const __half* __restrict__ xql,
                const __half* __restrict__ qBh, const __half* __restrict__ qBl,
                float* __restrict__ t0p, float* __restrict__ qbp) {
    extern __shared__ char smdyn[];
    int job = blockIdx.z >> 1, kz = blockIdx.z & 1;
    const __half *Ah = job ? xqh : xvh, *Al = job ? xql : xvl;
    const __half *Bh = job ? qBh : vBh, *Bl = job ? qBl : vBl;
    float* C = (job ? qbp : t0p) + (size_t)kz * BB * 512;
    gemm_core(Ah, Al, Bh, Bl, C, blockIdx.y * 128, blockIdx.x * 128, kz * 256, 512, 512, 8, smdyn);
}

// qW2 (full) + vW2 (splitk2) packed. grid (4, 416)
__global__ __launch_bounds__(512, 1)
void gemm_dualB(const __half* __restrict__ q1h, const __half* __restrict__ q1l,
                const __half* __restrict__ qBh, const __half* __restrict__ qBl,
                const __half* __restrict__ t1h, const __half* __restrict__ t1l,
                const __half* __restrict__ vBh, const __half* __restrict__ vBl,
                float* __restrict__ q2pre, float* __restrict__ t0p) {
    extern __shared__ char smdyn[];
    int y = blockIdx.y;
    if (y < 384) {
        gemm_core(q1h, q1l, qBh, qBl, q2pre, y * 128, blockIdx.x * 128, 0, 512, 512, 16, smdyn);
    } else {
        int j = y - 384, kz = j >> 4, y2 = j & 15;
        gemm_core(t1h, t1l, vBh, vBl, t0p + (size_t)kz * BB * 512,
                  y2 * 128, blockIdx.x * 128, kz * 256, 512, 512, 8, smdyn);
    }
}

// ===================== prep kernels =========================================
__global__ void split_f32(const float* __restrict__ x, __half* __restrict__ h,
                          __half* __restrict__ l, int n4) {
    int i = blockIdx.x * blockDim.x + threadIdx.x;
    if (i >= n4) return;
    float4 v = ((const float4*)x)[i];
    __half h0, l0, h1, l1, h2, l2, h3, l3;
    split_h(v.x, h0, l0); split_h(v.y, h1, l1);
    split_h(v.z, h2, l2); split_h(v.w, h3, l3);
    ((__half2*)h)[i * 2]     = __halves2half2(h0, h1);
    ((__half2*)h)[i * 2 + 1] = __halves2half2(h2, h3);
    ((__half2*)l)[i * 2]     = __halves2half2(l0, l1);
    ((__half2*)l)[i * 2 + 1] = __halves2half2(l2, l3);
}

// all four 512x512 weight transposes in one launch; z selects the job
__global__ void trans_split4(const float* __restrict__ W0, __half* __restrict__ T0h, __half* __restrict__ T0l,
                             const float* __restrict__ W1, __half* __restrict__ T1h, __half* __restrict__ T1l,
                             const float* __restrict__ W2, __half* __restrict__ T2h, __half* __restrict__ T2l,
                             const float* __restrict__ W3, __half* __restrict__ T3h, __half* __restrict__ T3l) {
    __shared__ float t[32][33];
    int z = blockIdx.z;
    const float* W = z == 0 ? W0 : z == 1 ? W1 : z == 2 ? W2 : W3;
    __half* Th = z == 0 ? T0h : z == 1 ? T1h : z == 2 ? T2h : T3h;
    __half* Tl = z == 0 ? T0l : z == 1 ? T1l : z == 2 ? T2l : T3l;
    int k0 = blockIdx.x * 32, n0 = blockIdx.y * 32;
    int tx = threadIdx.x, ty = threadIdx.y;
    #pragma unroll
    for (int i = 0; i < 4; i++)
        t[ty + i * 8][tx] = W[(size_t)(k0 + ty + i * 8) * 512 + n0 + tx];
    __syncthreads();
    #pragma unroll
    for (int i = 0; i < 4; i++) {
        float v = t[tx][ty + i * 8];
        __half h, l; split_h(v, h, l);
        size_t o = (size_t)(n0 + ty + i * 8) * 512 + k0 + tx;
        Th[o] = h; Tl[o] = l;
    }
}

__global__ void trans_split_rgb(const float* __restrict__ vW, const float* __restrict__ qW,
                                __half* __restrict__ Th, __half* __restrict__ Tl) {
    __shared__ float t[32][33];
    int k0 = blockIdx.x * 32, n0 = blockIdx.y * 32;
    int tx = threadIdx.x, ty = threadIdx.y;
    const float* src = (n0 < 256) ? vW : qW;
    int nb = (n0 < 256) ? n0 : (n0 - 256);
    #pragma unroll
    for (int i = 0; i < 4; i++)
        t[ty + i * 8][tx] = src[(size_t)(k0 + ty + i * 8) * 256 + nb + tx];
    __syncthreads();
    #pragma unroll
    for (int i = 0; i < 4; i++) {
        float v = t[tx][ty + i * 8];
        __half h, l; split_h(v, h, l);
        size_t o = (size_t)(n0 + ty + i * 8) * REPRK + k0 + tx;
        Th[o] = h; Tl[o] = l;
    }
}

// ===================== activation kernels ===================================
__global__ void ln_tanh_rgb(const float* __restrict__ part,
                            const float* __restrict__ vg, const float* __restrict__ vb,
                            const float* __restrict__ qg, const float* __restrict__ qb,
                            __half* __restrict__ xvh, __half* __restrict__ xvl,
                            __half* __restrict__ xqh, __half* __restrict__ xql) {
    int b = blockIdx.x, hsel = blockIdx.y, j = threadIdx.x;
    const size_t np = (size_t)BB * 512;
    size_t off = (size_t)b * 512 + hsel * 256 + j;
    float x = part[off] + part[off + np] + part[off + 2 * np] + part[off + 3 * np];
    float2 r = blockReduce2_256(make_float2(x, x * x));
    float mu = r.x * (1.f / 256.f);
    float inv = rsqrtf(r.y * (1.f / 256.f) - mu * mu + 1e-5f);
    const float* g  = hsel ? qg : vg;
    const float* be = hsel ? qb : vb;
    float y = tanhf((x - mu) * inv * g[j] + be[j]);
    __half h, l; split_h(y, h, l);
    if (hsel) { xqh[(size_t)b * 512 + j] = h; xql[(size_t)b * 512 + j] = l; }
    else      { xvh[(size_t)b * 512 + j] = h; xvl[(size_t)b * 512 + j] = l; }
}

__global__ void low_kernel(const float* __restrict__ low,
                           const float* __restrict__ vW, const float* __restrict__ vg, const float* __restrict__ vb,
                           const float* __restrict__ qW, const float* __restrict__ qg, const float* __restrict__ qb,
                           __half* __restrict__ xvh, __half* __restrict__ xvl,
                           __half* __restrict__ xqh, __half* __restrict__ xql) {
    int b = blockIdx.x, j = threadIdx.x;
    __shared__ float lo[32];
    if (j < 32) lo[j] = low[b * 32 + j];
    __syncthreads();
    float sv = 0.f, sq = 0.f;
    #pragma unroll 8
    for (int k = 0; k < 32; k++) {
        float l = lo[k];
        sv += l * vW[k * 256 + j];
        sq += l * qW[k * 256 + j];
    }
    float2 rv = blockReduce2_256(make_float2(sv, sv * sv));
    float muv = rv.x * (1.f / 256.f);
    float iv  = rsqrtf(rv.y * (1.f / 256.f) - muv * muv + 1e-5f);
    float yv = tanhf((sv - muv) * iv * vg[j] + vb[j]);
    __half h, l; split_h(yv, h, l);
    xvh[(size_t)b * 512 + 256 + j] = h; xvl[(size_t)b * 512 + 256 + j] = l;
    float2 rq = blockReduce2_256(make_float2(sq, sq * sq));
    float muq = rq.x * (1.f / 256.f);
    float iq  = rsqrtf(rq.y * (1.f / 256.f) - muq * muq + 1e-5f);
    float yq = tanhf((sq - muq) * iq * qg[j] + qb[j]);
    split_h(yq, h, l);
    xqh[(size_t)b * 512 + 256 + j] = h; xql[(size_t)b * 512 + 256 + j] = l;
}

// one thread per (b, s): contiguous 32B stores, recompute mids from cat
__global__ void act_kernel(const int* __restrict__ cat, float* __restrict__ act) {
    int t = blockIdx.x * blockDim.x + threadIdx.x;
    if (t >= BB * SS) return;
    int b = t / SS, k = t - b * SS;
    int ls = k >> 3, ds = k & 7;
    float out[8];
    #pragma unroll
    for (int d = 0; d < 8; d++) {
        int lvl = ls + (d < ds ? 1 : 0);   // 0..3 ; 0 => zero
        float lowv = -1.f, width = 2.f, mid = 0.f;
        for (int l = 0; l < lvl; l++) {
            float w = width * (1.f / 16.f);
            float c = (float)cat[(b * 3 + l) * 8 + d];
            float nl = lowv + c * w;
            mid = nl + 0.5f * w;
            lowv = nl; width = w;
        }
        out[d] = (lvl == 0) ? 0.f : mid;
    }
    float4* dst = (float4*)&act[(size_t)t * 8];
    dst[0] = make_float4(out[0], out[1], out[2], out[3]);
    dst[1] = make_float4(out[4], out[5], out[6], out[7]);
}

// blocks [0,2048): q1_all (reads qbp partials); [2048,4096): ln_silu_split (t0p)
__global__ __launch_bounds__(256)
void mid_k(const float* __restrict__ qbp, const float* __restrict__ act,
           const float* __restrict__ qW1, const float* __restrict__ qg1, const float* __restrict__ qb1,
           const float* __restrict__ t0p, const float* __restrict__ vg1, const float* __restrict__ vb1,
           __half* __restrict__ q1h, __half* __restrict__ q1l,
           __half* __restrict__ t1h, __half* __restrict__ t1l) {
    const size_t np = (size_t)BB * 512;
    int j = threadIdx.x;
    if (blockIdx.x < BB) {
        __shared__ float wact[8 * 512];
        __shared__ float as[SS * DD];
        int b = blockIdx.x;
        for (int i = j; i < 8 * 512; i += 256)
            wact[i] = qW1[(size_t)(512 + (i >> 9)) * 512 + (i & 511)];
        for (int i = j; i < SS * DD; i += 256)
            as[i] = act[(size_t)b * SS * DD + i];
        float b0 = qbp[(size_t)b * 512 + j]       + qbp[np + (size_t)b * 512 + j];
        float b1 = qbp[(size_t)b * 512 + 256 + j] + qbp[np + (size_t)b * 512 + 256 + j];
        float g0 = qg1[j], g1 = qg1[j + 256], e0 = qb1[j], e1 = qb1[j + 256];
        __syncthreads();
        for (int s = 0; s < SS; s++) {
            float x0 = b0, x1 = b1;
            #pragma unroll
            for (int d = 0; d < 8; d++) {
                float av = as[s * 8 + d];
                x0 += av * wact[d * 512 + j];
                x1 += av * wact[d * 512 + 256 + j];
            }
            float2 r = blockReduce2_256(make_float2(x0 + x1, x0 * x0 + x1 * x1));
            float mu = r.x * (1.f / 512.f);
            float inv = rsqrtf(r.y * (1.f / 512.f) - mu * mu + 1e-5f);
            float y0 = silu((x0 - mu) * inv * g0 + e0);
            float y1 = silu((x1 - mu) * inv * g1 + e1);
            size_t row = (size_t)s * BB + b;
            __half h, l;
            split_h(y0, h, l); q1h[row * 512 + j] = h;       q1l[row * 512 + j] = l;
            split_h(y1, h, l); q1h[row * 512 + 256 + j] = h; q1l[row * 512 + 256 + j] = l;
        }
    } else {
        size_t row = blockIdx.x - BB;
        float x0 = t0p[row * 512 + j]       + t0p[np + row * 512 + j];
        float x1 = t0p[row * 512 + 256 + j] + t0p[np + row * 512 + 256 + j];
        float2 r = blockReduce2_256(make_float2(x0 + x1, x0 * x0 + x1 * x1));
        float mu = r.x * (1.f / 512.f);
        float inv = rsqrtf(r.y * (1.f / 512.f) - mu * mu + 1e-5f);
        float y0 = silu((x0 - mu) * inv * vg1[j] + vb1[j]);
        float y1 = silu((x1 - mu) * inv * vg1[j + 256] + vb1[j + 256]);
        __half h, l;
        split_h(y0, h, l); t1h[row * 512 + j] = h;       t1l[row * 512 + j] = l;
        split_h(y1, h, l); t1h[row * 512 + 256 + j] = h; t1l[row * 512 + 256 + j] = l;
    }
}

// vW2 partials -> LN -> SiLU -> value head, one block per b
__global__ __launch_bounds__(256)
void vfin(const float* __restrict__ t0p, const float* __restrict__ g,
          const float* __restrict__ be, const float* __restrict__ Wh,
          const float* __restrict__ bh, float* __restrict__ out) {
    const size_t np = (size_t)BB * 512;
    int b = blockIdx.x, j = threadIdx.x;
    float x0 = t0p[(size_t)b * 512 + j]       + t0p[np + (size_t)b * 512 + j];
    float x1 = t0p[(size_t)b * 512 + 256 + j] + t0p[np + (size_t)b * 512 + 256 + j];
    float2 r = blockReduce2_256(make_float2(x0 + x1, x0 * x0 + x1 * x1));
    float mu = r.x * (1.f / 512.f);
    float inv = rsqrtf(r.y * (1.f / 512.f) - mu * mu + 1e-5f);
    float y0 = silu((x0 - mu) * inv * g[j] + be[j]);
    float y1 = silu((x1 - mu) * inv * g[j + 256] + be[j + 256]);
    float s = y0 * Wh[j] + y1 * Wh[256 + j];
    float2 r2 = blockReduce2_256(make_float2(s, 0.f));
    if (j == 0) out[b] = r2.x + bh[0];
}

// ---- fused LN + SiLU + diagonal q-head over q2pre (s-major rows) ----------
#define YSLD 520
__global__ __launch_bounds__(256)
void lnhead_q(const float* __restrict__ pre, const float* __restrict__ g,
              const float* __restrict__ be, const float* __restrict__ Wh,
              const float* __restrict__ bh, float* __restrict__ out) {
    extern __shared__ float sm[];
    float* whs = sm;             // [512][16]
    float* ys  = sm + 512 * 16;  // [64][YSLD]
    const int tid = threadIdx.x, lane = tid & 31, w = tid >> 5;
    const int r0 = blockIdx.x * 64;
    const int s16 = (r0 >> 11) * 16;

    for (int i = tid; i < 512 * 16; i += 256)
        whs[i] = Wh[(size_t)(i >> 4) * SBH + s16 + (i & 15)];

    for (int rr = w; rr < 64; rr += 8) {
        const float* row = pre + (size_t)(r0 + rr) * 512;
        float v[16];
        float s1 = 0.f, s2 = 0.f;
        #pragma unroll
        for (int i = 0; i < 16; i++) {
            v[i] = row[lane + i * 32];
            s1 += v[i]; s2 += v[i] * v[i];
        }
        #pragma unroll
        for (int o = 16; o > 0; o >>= 1) {
            s1 += __shfl_xor_sync(0xffffffffu, s1, o);
            s2 += __shfl_xor_sync(0xffffffffu, s2, o);
        }
        float mu = s1 * (1.f / 512.f);
        float inv = rsqrtf(s2 * (1.f / 512.f) - mu * mu + 1e-5f);
        #pragma unroll
        for (int i = 0; i < 16; i++) {
            int col = lane + i * 32;
            ys[rr * YSLD + col] = silu((v[i] - mu) * inv * g[col] + be[col]);
        }
    }
    __syncthreads();

    const int rid = tid >> 3, c2 = tid & 7;
    const float2 bias = *(const float2*)&bh[s16 + c2 * 2];
    float a0 = 0.f, a1 = 0.f, c0 = 0.f, c1 = 0.f;
    const float* y0r = ys + rid * YSLD;
    const float* y1r = ys + (rid + 32) * YSLD;
    #pragma unroll 8
    for (int k = 0; k < 512; k++) {
        float2 w2 = *(const float2*)&whs[k * 16 + c2 * 2];
        float ya = y0r[k], yb = y1r[k];
        a0 += ya * w2.x; a1 += ya * w2.y;
        c0 += yb * w2.x; c1 += yb * w2.y;
    }
    int brow0 = (r0 + rid) & (BB - 1);
    int brow1 = (r0 + rid + 32) & (BB - 1);
    *(float2*)&out[(size_t)brow0 * SBH + s16 + c2 * 2] = make_float2(a0 + bias.x, a1 + bias.y);
    *(float2*)&out[(size_t)brow1 * SBH + s16 + c2 * 2] = make_float2(c0 + bias.x, c1 + bias.y);
}

// ===================== launch ================================================
#define GEMM_DSMEM 65536
#define LNHEAD_DSMEM ((512 * 16 + 64 * YSLD) * 4)

extern "C" void kernel_launch(void* const* d_in, const int* in_sizes, int n_in,
                              void* d_out, int out_size) {
    const float* rgb_obs = (const float*)d_in[0];
    const float* low_obs = (const float*)d_in[1];
    const int*   category = (const int*)d_in[2];
    const float* v_W_rgb = (const float*)d_in[3];
    const float* v_g_rgb = (const float*)d_in[4];
    const float* v_b_rgb = (const float*)d_in[5];
    const float* v_W_low = (const float*)d_in[6];
    const float* v_g_low = (const float*)d_in[7];
    const float* v_b_low = (const float*)d_in[8];
    const float* v_W1 = (const float*)d_in[9];
    const float* v_g1 = (const float*)d_in[10];
    const float* v_b1 = (const float*)d_in[11];
    const float* v_W2 = (const float*)d_in[12];
    const float* v_g2 = (const float*)d_in[13];
    const float* v_b2 = (const float*)d_in[14];
    const float* v_Wh = (const float*)d_in[15];
    const float* v_bh = (const float*)d_in[16];
    const float* q_W_rgb = (const float*)d_in[17];
    const float* q_g_rgb = (const float*)d_in[18];
    const float* q_b_rgb = (const float*)d_in[19];
    const float* q_W_low = (const float*)d_in[20];
    const float* q_g_low = (const float*)d_in[21];
    const float* q_b_low = (const float*)d_in[22];
    const float* q_W1 = (const float*)d_in[23];
    const float* q_g1 = (const float*)d_in[24];
    const float* q_b1 = (const float*)d_in[25];
    const float* q_W2 = (const float*)d_in[26];
    const float* q_g2 = (const float*)d_in[27];
    const float* q_b2 = (const float*)d_in[28];
    const float* q_Wh = (const float*)d_in[29];
    const float* q_bh = (const float*)d_in[30];

    float* out_value = (float*)d_out;
    float* out_adv   = out_value + BB;

    cudaFuncSetAttribute(gemm_rgb,   cudaFuncAttributeMaxDynamicSharedMemorySize, GEMM_DSMEM);
    cudaFuncSetAttribute(gemm_dualA, cudaFuncAttributeMaxDynamicSharedMemorySize, GEMM_DSMEM);
    cudaFuncSetAttribute(gemm_dualB, cudaFuncAttributeMaxDynamicSharedMemorySize, GEMM_DSMEM);
    cudaFuncSetAttribute(lnhead_q,   cudaFuncAttributeMaxDynamicSharedMemorySize, LNHEAD_DSMEM);

    __half *Ahi, *Alo, *WrgbTh, *WrgbTl, *xvh, *xvl, *xqh, *xql;
    __half *vW1Th, *vW1Tl, *vW2Th, *vW2Tl, *qW1Th, *qW1Tl, *qW2Th, *qW2Tl;
    __half *t1h, *t1l, *q1h, *q1l;
    float *rgb_part, *act, *q2pre;
    cudaGetSymbolAddress((void**)&Ahi, g_Ahi);       cudaGetSymbolAddress((void**)&Alo, g_Alo);
    cudaGetSymbolAddress((void**)&WrgbTh, g_WrgbTh); cudaGetSymbolAddress((void**)&WrgbTl, g_WrgbTl);
    cudaGetSymbolAddress((void**)&rgb_part, g_rgb_part);
    cudaGetSymbolAddress((void**)&xvh, g_xvh); cudaGetSymbolAddress((void**)&xvl, g_xvl);
    cudaGetSymbolAddress((void**)&xqh, g_xqh); cudaGetSymbolAddress((void**)&xql, g_xql);
    cudaGetSymbolAddress((void**)&vW1Th, g_vW1Th); cudaGetSymbolAddress((void**)&vW1Tl, g_vW1Tl);
    cudaGetSymbolAddress((void**)&vW2Th, g_vW2Th); cudaGetSymbolAddress((void**)&vW2Tl, g_vW2Tl);
    cudaGetSymbolAddress((void**)&qW1Th, g_qW1Th); cudaGetSymbolAddress((void**)&qW1Tl, g_qW1Tl);
    cudaGetSymbolAddress((void**)&qW2Th, g_qW2Th); cudaGetSymbolAddress((void**)&qW2Tl, g_qW2Tl);
    cudaGetSymbolAddress((void**)&t1h, g_t1h); cudaGetSymbolAddress((void**)&t1l, g_t1l);
    cudaGetSymbolAddress((void**)&act, g_act);
    cudaGetSymbolAddress((void**)&q1h, g_q1h); cudaGetSymbolAddress((void**)&q1l, g_q1l);
    cudaGetSymbolAddress((void**)&q2pre, g_q2pre);

    float* t0p = rgb_part;                        // slices 0,1
    float* qbp = rgb_part + 2 * (size_t)BB * 512; // slices 2,3

    // ---- prep ----
    act_kernel<<<(BB * SS + 255) / 256, 256>>>(category, act);
    split_f32<<<(BB * REPRK / 4 + 255) / 256, 256>>>(rgb_obs, Ahi, Alo, BB * REPRK / 4);
    trans_split_rgb<<<dim3(REPRK / 32, 512 / 32), dim3(32, 8)>>>(v_W_rgb, q_W_rgb, WrgbTh, WrgbTl);
    trans_split4<<<dim3(16, 16, 4), dim3(32, 8)>>>(v_W1, vW1Th, vW1Tl, v_W2, vW2Th, vW2Tl,
                                                   q_W1, qW1Th, qW1Tl, q_W2, qW2Th, qW2Tl);

    // ---- shared rgb features: split-K=4 over K=8192, reduce folded into LN ----
    gemm_rgb<<<dim3(4, BB / 128, 4), 512, GEMM_DSMEM>>>(Ahi, Alo, WrgbTh, WrgbTl, rgb_part);
    ln_tanh_rgb<<<dim3(BB, 2), 256>>>(rgb_part, v_g_rgb, v_b_rgb, q_g_rgb, q_b_rgb,
                                      xvh, xvl, xqh, xql);
    low_kernel<<<BB, 256>>>(low_obs, v_W_low, v_g_low, v_b_low, q_W_low, q_g_low, q_b_low,
                            xvh, xvl, xqh, xql);

    // ---- layer 1 (v + q packed, split-K=2 each) ----
    gemm_dualA<<<dim3(4, 16, 4), 512, GEMM_DSMEM>>>(xvh, xvl, vW1Th, vW1Tl,
                                                    xqh, xql, qW1Th, qW1Tl, t0p, qbp);
    // ---- q1 expansion + v ln_silu in one launch ----
    mid_k<<<2 * BB, 256>>>(qbp, act, q_W1, q_g1, q_b1, t0p, v_g1, v_b1,
                           q1h, q1l, t1h, t1l);

    // ---- layer 2: qW2 (big) + vW2 (splitk2) packed ----
    gemm_dualB<<<dim3(4, 416), 512, GEMM_DSMEM>>>(q1h, q1l, qW2Th, qW2Tl,
                                                  t1h, t1l, vW2Th, vW2Tl, q2pre, t0p);

    // ---- heads ----
    vfin<<<BB, 256>>>(t0p, v_g2, v_b2, v_Wh, v_bh, out_value);
    lnhead_q<<<(BB * SS) / 64, 256, LNHEAD_DSMEM>>>(q2pre, q_g2, q_b2, q_Wh, q_bh, out_adv);
}

// round 10
// speedup vs baseline: 2.0298x; 1.2941x over previous
#include <cuda_runtime.h>
#include <cuda_fp16.h>
#include <stdint.h>
#include <math.h>

#define BB    2048
#define REPRK 8192
#define SS    24
#define DD    8
#define SBH   384   // S*BINS

// ===================== PTX helpers (non-arch-specific) ======================
__device__ __forceinline__ uint32_t smem_u32(const void* p) {
    uint32_t a;
    asm("{ .reg .u64 t; cvta.to.shared.u64 t, %1; cvt.u32.u64 %0, t; }" : "=r"(a) : "l"(p));
    return a;
}
__device__ __forceinline__ void cp16(uint32_t saddr, const void* g) {
    asm volatile("cp.async.cg.shared.global [%0], [%1], 16;" :: "r"(saddr), "l"(g));
}
#define CPCOMMIT asm volatile("cp.async.commit_group;" ::: "memory")
#define CPWAIT1  asm volatile("cp.async.wait_group 1;" ::: "memory")

__device__ __forceinline__ void ldsm4(uint32_t* r, uint32_t addr) {
    asm volatile("ldmatrix.sync.aligned.m8n8.x4.shared.b16 {%0,%1,%2,%3}, [%4];"
        : "=r"(r[0]), "=r"(r[1]), "=r"(r[2]), "=r"(r[3]) : "r"(addr));
}
// fp16 inputs, f32 accumulator (main pass)
__device__ __forceinline__ void mma_f32acc(float* d, const uint32_t* a, uint32_t b0, uint32_t b1) {
    asm volatile("mma.sync.aligned.m16n8k16.row.col.f32.f16.f16.f32 "
        "{%0,%1,%2,%3}, {%4,%5,%6,%7}, {%8,%9}, {%0,%1,%2,%3};"
        : "+f"(d[0]), "+f"(d[1]), "+f"(d[2]), "+f"(d[3])
        : "r"(a[0]), "r"(a[1]), "r"(a[2]), "r"(a[3]), "r"(b0), "r"(b1));
}
// fp16 inputs, f16 accumulator (weight-lo correction pass)
__device__ __forceinline__ void mma_f16acc(uint32_t* d, const uint32_t* a, uint32_t b0, uint32_t b1) {
    asm volatile("mma.sync.aligned.m16n8k16.row.col.f16.f16.f16.f16 "
        "{%0,%1}, {%2,%3,%4,%5}, {%6,%7}, {%0,%1};"
        : "+r"(d[0]), "+r"(d[1])
        : "r"(a[0]), "r"(a[1]), "r"(a[2]), "r"(a[3]), "r"(b0), "r"(b1));
}

// ===================== scratch (device globals) =============================
__device__ __half g_Ahi[(size_t)BB * REPRK];       // 32 MB
__device__ __half g_WrgbTh[(size_t)512 * REPRK];   // 8 MB
__device__ __half g_WrgbTl[(size_t)512 * REPRK];
__device__ float g_rgb_part[4 * BB * 512];         // 16 MB: rgb splitk, then t0p/qbp
__device__ __half g_xvh[BB * 512];
__device__ __half g_xqh[BB * 512];
__device__ __half g_vW1Th[512 * 512], g_vW1Tl[512 * 512];
__device__ __half g_vW2Th[512 * 512], g_vW2Tl[512 * 512];
__device__ __half g_qW1Th[512 * 512], g_qW1Tl[512 * 512];
__device__ __half g_qW2Th[512 * 512], g_qW2Tl[512 * 512];
__device__ __half g_t1h[BB * 512];
__device__ float g_act[BB * SS * DD];
__device__ __half g_q1h[(size_t)BB * SS * 512];    // 50 MB (s-major rows)
__device__ float g_q2pre[(size_t)BB * SS * 512];   // 100 MB (s-major rows)

// ===================== small helpers ========================================
__device__ __forceinline__ void split_h(float x, __half& h, __half& l) {
    h = __float2half_rn(x);
    l = __float2half_rn(x - __half2float(h));
}
__device__ __forceinline__ float silu(float z) { return z / (1.f + expf(-z)); }

__device__ __forceinline__ float2 blockReduce2_256(float2 v) {
    __shared__ float2 sm[8];
    int lane = threadIdx.x & 31, w = threadIdx.x >> 5;
    #pragma unroll
    for (int o = 16; o > 0; o >>= 1) {
        v.x += __shfl_xor_sync(0xffffffffu, v.x, o);
        v.y += __shfl_xor_sync(0xffffffffu, v.y, o);
    }
    if (lane == 0) sm[w] = v;
    __syncthreads();
    if (threadIdx.x == 0) {
        float2 t = sm[0];
        #pragma unroll
        for (int i = 1; i < 8; i++) { t.x += sm[i].x; t.y += sm[i].y; }
        sm[0] = t;
    }
    __syncthreads();
    float2 r = sm[0];
    __syncthreads();
    return r;
}

// ===================== HMMA 2-pass GEMM core (128x128 tile) =================
// pass1 (f32 acc): A*Bh^T ; pass2 (f16 acc): A*Bl^T  (A already fp16-rounded)
__device__ __forceinline__ void gemm_core(
    const __half* __restrict__ A,
    const __half* __restrict__ Bh, const __half* __restrict__ Bl,
    float* __restrict__ C, int m0, int n0, int kbase, int lda, int N, int nch,
    char* smdyn) {
    const int tid = threadIdx.x;
    const int lane = tid & 31, wid = tid >> 5;
    const int wm = wid & 3, wn = wid >> 2;

    const int lrow = tid >> 2, lc = tid & 3;
    const int lpc = lc ^ ((lrow >> 1) & 3);
    const uint32_t sb0 = smem_u32(smdyn);
    const uint32_t s_store = sb0 + lrow * 64 + lpc * 16;
    const __half* gA  = A  + (size_t)(m0 + lrow) * lda + kbase + lc * 8;
    const __half* gBh = Bh + (size_t)(n0 + lrow) * lda + kbase + lc * 8;
    const __half* gBl = Bl + (size_t)(n0 + lrow) * lda + kbase + lc * 8;

#define LOADST(s, i) do { \
    uint32_t _so = s_store + (uint32_t)(s) * 24576u; \
    size_t _ko = (size_t)(i) * 32; \
    cp16(_so,          gA  + _ko); \
    cp16(_so +  8192,  gBh + _ko); \
    cp16(_so + 16384,  gBl + _ko); } while (0)

    LOADST(0, 0); CPCOMMIT;
    LOADST(1, 1); CPCOMMIT;

    float acc[2][4][4];
    uint32_t cor[2][4][2];
    #pragma unroll
    for (int mf = 0; mf < 2; mf++)
        #pragma unroll
        for (int nf = 0; nf < 4; nf++) {
            #pragma unroll
            for (int r = 0; r < 4; r++) acc[mf][nf][r] = 0.f;
            cor[mf][nf][0] = 0u; cor[mf][nf][1] = 0u;
        }

    const int r15 = lane & 15, ksel = lane >> 4;

    for (int i = 0; i < nch; i++) {
        CPWAIT1;
        __syncthreads();
        uint32_t sb = sb0 + (uint32_t)(i & 1) * 24576u;
        #pragma unroll
        for (int kt = 0; kt < 2; kt++) {
            const int cA = 2 * kt + ksel;
            uint32_t a[2][4], bh[2][4], bl[2][4];
            #pragma unroll
            for (int mf = 0; mf < 2; mf++) {
                int row = wm * 32 + mf * 16 + r15;
                uint32_t off = (uint32_t)(row * 64 + ((cA ^ ((row >> 1) & 3)) * 16));
                ldsm4(a[mf], sb + off);
            }
            #pragma unroll
            for (int nf2 = 0; nf2 < 2; nf2++) {
                int row = wn * 32 + nf2 * 16 + r15;
                uint32_t off = (uint32_t)(row * 64 + ((cA ^ ((row >> 1) & 3)) * 16));
                ldsm4(bh[nf2], sb + 8192 + off);
                ldsm4(bl[nf2], sb + 16384 + off);
            }
            #pragma unroll
            for (int mf = 0; mf < 2; mf++)
                #pragma unroll
                for (int nf = 0; nf < 4; nf++) {
                    mma_f32acc(acc[mf][nf], a[mf], bh[nf >> 1][nf & 1], bh[nf >> 1][2 + (nf & 1)]);
                    mma_f16acc(cor[mf][nf], a[mf], bl[nf >> 1][nf & 1], bl[nf >> 1][2 + (nf & 1)]);
                }
        }
        __syncthreads();
        if (i + 2 < nch) LOADST(i & 1, i + 2);
        CPCOMMIT;
    }
#undef LOADST

    #pragma unroll
    for (int mf = 0; mf < 2; mf++)
        #pragma unroll
        for (int nf = 0; nf < 4; nf++) {
            int m = m0 + wm * 32 + mf * 16 + (lane >> 2);
            int n = n0 + wn * 32 + nf * 8 + (lane & 3) * 2;
            __half2 c01 = *(__half2*)&cor[mf][nf][0];
            __half2 c23 = *(__half2*)&cor[mf][nf][1];
            *(float2*)&C[(size_t)m * N + n] =
                make_float2(acc[mf][nf][0] + __low2float(c01), acc[mf][nf][1] + __high2float(c01));
            *(float2*)&C[(size_t)(m + 8) * N + n] =
                make_float2(acc[mf][nf][2] + __low2float(c23), acc[mf][nf][3] + __high2float(c23));
        }
}

// rgb GEMM: grid (4, 16, 4) splitk over K=8192
__global__ __launch_bounds__(512, 1)
void gemm_rgb(const __half* __restrict__ A,
              const __half* __restrict__ Bh, const __half* __restrict__ Bl,
              float* __restrict__ C) {
    extern __shared__ char smdyn[];
    gemm_core(A, Bh, Bl, C + (size_t)blockIdx.z * BB * 512,
              blockIdx.y * 128, blockIdx.x * 128, blockIdx.z * 2048, REPRK, 512, 64, smdyn);
}

// vW1 + qW1 packed, each splitk2. grid (4, 16, 4): z = job*2 + kz
__global__ __launch_bounds__(512, 1)
void gemm_dualA(const __half* __restrict__ xvh,
                const __half* __restrict__ vBh, const __half* __restrict__ vBl,
                const __half* __restrict__ xqh,
                const __half* __restrict__ qBh, const __half* __restrict__ qBl,
                float* __restrict__ t0p, float* __restrict__ qbp) {
    extern __shared__ char smdyn[];
    int job = blockIdx.z >> 1, kz = blockIdx.z & 1;
    const __half* A  = job ? xqh : xvh;
    const __half* Bh = job ? qBh : vBh;
    const __half* Bl = job ? qBl : vBl;
    float* C = (job ? qbp : t0p) + (size_t)kz * BB * 512;
    gemm_core(A, Bh, Bl, C, blockIdx.y * 128, blockIdx.x * 128, kz * 256, 512, 512, 8, smdyn);
}

// qW2 (full) + vW2 (splitk2) packed. grid (4, 416)
__global__ __launch_bounds__(512, 1)
void gemm_dualB(const __half* __restrict__ q1h,
                const __half* __restrict__ qBh, const __half* __restrict__ qBl,
                const __half* __restrict__ t1h,
                const __half* __restrict__ vBh, const __half* __restrict__ vBl,
                float* __restrict__ q2pre, float* __restrict__ t0p) {
    extern __shared__ char smdyn[];
    int y = blockIdx.y;
    if (y < 384) {
        gemm_core(q1h, qBh, qBl, q2pre, y * 128, blockIdx.x * 128, 0, 512, 512, 16, smdyn);
    } else {
        int j = y - 384, kz = j >> 4, y2 = j & 15;
        gemm_core(t1h, vBh, vBl, t0p + (size_t)kz * BB * 512,
                  y2 * 128, blockIdx.x * 128, kz * 256, 512, 512, 8, smdyn);
    }
}

// ===================== prep kernels =========================================
// rgb_obs f32 -> fp16 (hi only)
__global__ void conv_hi(const float* __restrict__ x, __half* __restrict__ h, int n4) {
    int i = blockIdx.x * blockDim.x + threadIdx.x;
    if (i >= n4) return;
    float4 v = ((const float4*)x)[i];
    ((__half2*)h)[i * 2]     = __halves2half2(__float2half_rn(v.x), __float2half_rn(v.y));
    ((__half2*)h)[i * 2 + 1] = __halves2half2(__float2half_rn(v.z), __float2half_rn(v.w));
}

// all four 512x512 weight transposes in one launch; z selects the job
__global__ void trans_split4(const float* __restrict__ W0, __half* __restrict__ T0h, __half* __restrict__ T0l,
                             const float* __restrict__ W1, __half* __restrict__ T1h, __half* __restrict__ T1l,
                             const float* __restrict__ W2, __half* __restrict__ T2h, __half* __restrict__ T2l,
                             const float* __restrict__ W3, __half* __restrict__ T3h, __half* __restrict__ T3l) {
    __shared__ float t[32][33];
    int z = blockIdx.z;
    const float* W = z == 0 ? W0 : z == 1 ? W1 : z == 2 ? W2 : W3;
    __half* Th = z == 0 ? T0h : z == 1 ? T1h : z == 2 ? T2h : T3h;
    __half* Tl = z == 0 ? T0l : z == 1 ? T1l : z == 2 ? T2l : T3l;
    int k0 = blockIdx.x * 32, n0 = blockIdx.y * 32;
    int tx = threadIdx.x, ty = threadIdx.y;
    #pragma unroll
    for (int i = 0; i < 4; i++)
        t[ty + i * 8][tx] = W[(size_t)(k0 + ty + i * 8) * 512 + n0 + tx];
    __syncthreads();
    #pragma unroll
    for (int i = 0; i < 4; i++) {
        float v = t[tx][ty + i * 8];
        __half h, l; split_h(v, h, l);
        size_t o = (size_t)(n0 + ty + i * 8) * 512 + k0 + tx;
        Th[o] = h; Tl[o] = l;
    }
}

__global__ void trans_split_rgb(const float* __restrict__ vW, const float* __restrict__ qW,
                                __half* __restrict__ Th, __half* __restrict__ Tl) {
    __shared__ float t[32][33];
    int k0 = blockIdx.x * 32, n0 = blockIdx.y * 32;
    int tx = threadIdx.x, ty = threadIdx.y;
    const float* src = (n0 < 256) ? vW : qW;
    int nb = (n0 < 256) ? n0 : (n0 - 256);
    #pragma unroll
    for (int i = 0; i < 4; i++)
        t[ty + i * 8][tx] = src[(size_t)(k0 + ty + i * 8) * 256 + nb + tx];
    __syncthreads();
    #pragma unroll
    for (int i = 0; i < 4; i++) {
        float v = t[tx][ty + i * 8];
        __half h, l; split_h(v, h, l);
        size_t o = (size_t)(n0 + ty + i * 8) * REPRK + k0 + tx;
        Th[o] = h; Tl[o] = l;
    }
}

// ===================== activation kernels ===================================
__global__ void ln_tanh_rgb(const float* __restrict__ part,
                            const float* __restrict__ vg, const float* __restrict__ vb,
                            const float* __restrict__ qg, const float* __restrict__ qb,
                            __half* __restrict__ xvh, __half* __restrict__ xqh) {
    int b = blockIdx.x, hsel = blockIdx.y, j = threadIdx.x;
    const size_t np = (size_t)BB * 512;
    size_t off = (size_t)b * 512 + hsel * 256 + j;
    float x = part[off] + part[off + np] + part[off + 2 * np] + part[off + 3 * np];
    float2 r = blockReduce2_256(make_float2(x, x * x));
    float mu = r.x * (1.f / 256.f);
    float inv = rsqrtf(r.y * (1.f / 256.f) - mu * mu + 1e-5f);
    const float* g  = hsel ? qg : vg;
    const float* be = hsel ? qb : vb;
    float y = tanhf((x - mu) * inv * g[j] + be[j]);
    __half* dst = hsel ? xqh : xvh;
    dst[(size_t)b * 512 + j] = __float2half_rn(y);
}

__global__ void low_kernel(const float* __restrict__ low,
                           const float* __restrict__ vW, const float* __restrict__ vg, const float* __restrict__ vb,
                           const float* __restrict__ qW, const float* __restrict__ qg, const float* __restrict__ qb,
                           __half* __restrict__ xvh, __half* __restrict__ xqh) {
    int b = blockIdx.x, j = threadIdx.x;
    __shared__ float lo[32];
    if (j < 32) lo[j] = low[b * 32 + j];
    __syncthreads();
    float sv = 0.f, sq = 0.f;
    #pragma unroll 8
    for (int k = 0; k < 32; k++) {
        float l = lo[k];
        sv += l * vW[k * 256 + j];
        sq += l * qW[k * 256 + j];
    }
    float2 rv = blockReduce2_256(make_float2(sv, sv * sv));
    float muv = rv.x * (1.f / 256.f);
    float iv  = rsqrtf(rv.y * (1.f / 256.f) - muv * muv + 1e-5f);
    xvh[(size_t)b * 512 + 256 + j] = __float2half_rn(tanhf((sv - muv) * iv * vg[j] + vb[j]));
    float2 rq = blockReduce2_256(make_float2(sq, sq * sq));
    float muq = rq.x * (1.f / 256.f);
    float iq  = rsqrtf(rq.y * (1.f / 256.f) - muq * muq + 1e-5f);
    xqh[(size_t)b * 512 + 256 + j] = __float2half_rn(tanhf((sq - muq) * iq * qg[j] + qb[j]));
}

// one thread per (b, s): contiguous 32B stores
__global__ void act_kernel(const int* __restrict__ cat, float* __restrict__ act) {
    int t = blockIdx.x * blockDim.x + threadIdx.x;
    if (t >= BB * SS) return;
    int b = t / SS, k = t - b * SS;
    int ls = k >> 3, ds = k & 7;
    float out[8];
    #pragma unroll
    for (int d = 0; d < 8; d++) {
        int lvl = ls + (d < ds ? 1 : 0);
        float lowv = -1.f, width = 2.f, mid = 0.f;
        for (int l = 0; l < lvl; l++) {
            float w = width * (1.f / 16.f);
            float c = (float)cat[(b * 3 + l) * 8 + d];
            float nl = lowv + c * w;
            mid = nl + 0.5f * w;
            lowv = nl; width = w;
        }
        out[d] = (lvl == 0) ? 0.f : mid;
    }
    float4* dst = (float4*)&act[(size_t)t * 8];
    dst[0] = make_float4(out[0], out[1], out[2], out[3]);
    dst[1] = make_float4(out[4], out[5], out[6], out[7]);
}

// blocks [0,2048): q1_all (reads qbp partials); [2048,4096): ln_silu (t0p)
__global__ __launch_bounds__(256)
void mid_k(const float* __restrict__ qbp, const float* __restrict__ act,
           const float* __restrict__ qW1, const float* __restrict__ qg1, const float* __restrict__ qb1,
           const float* __restrict__ t0p, const float* __restrict__ vg1, const float* __restrict__ vb1,
           __half* __restrict__ q1h, __half* __restrict__ t1h) {
    const size_t np = (size_t)BB * 512;
    int j = threadIdx.x;
    if (blockIdx.x < BB) {
        __shared__ float wact[8 * 512];
        __shared__ float as[SS * DD];
        int b = blockIdx.x;
        for (int i = j; i < 8 * 512; i += 256)
            wact[i] = qW1[(size_t)(512 + (i >> 9)) * 512 + (i & 511)];
        for (int i = j; i < SS * DD; i += 256)
            as[i] = act[(size_t)b * SS * DD + i];
        float b0 = qbp[(size_t)b * 512 + j]       + qbp[np + (size_t)b * 512 + j];
        float b1 = qbp[(size_t)b * 512 + 256 + j] + qbp[np + (size_t)b * 512 + 256 + j];
        float g0 = qg1[j], g1 = qg1[j + 256], e0 = qb1[j], e1 = qb1[j + 256];
        __syncthreads();
        for (int s = 0; s < SS; s++) {
            float x0 = b0, x1 = b1;
            #pragma unroll
            for (int d = 0; d < 8; d++) {
                float av = as[s * 8 + d];
                x0 += av * wact[d * 512 + j];
                x1 += av * wact[d * 512 + 256 + j];
            }
            float2 r = blockReduce2_256(make_float2(x0 + x1, x0 * x0 + x1 * x1));
            float mu = r.x * (1.f / 512.f);
            float inv = rsqrtf(r.y * (1.f / 512.f) - mu * mu + 1e-5f);
            size_t row = (size_t)s * BB + b;
            q1h[row * 512 + j]       = __float2half_rn(silu((x0 - mu) * inv * g0 + e0));
            q1h[row * 512 + 256 + j] = __float2half_rn(silu((x1 - mu) * inv * g1 + e1));
        }
    } else {
        size_t row = blockIdx.x - BB;
        float x0 = t0p[row * 512 + j]       + t0p[np + row * 512 + j];
        float x1 = t0p[row * 512 + 256 + j] + t0p[np + row * 512 + 256 + j];
        float2 r = blockReduce2_256(make_float2(x0 + x1, x0 * x0 + x1 * x1));
        float mu = r.x * (1.f / 512.f);
        float inv = rsqrtf(r.y * (1.f / 512.f) - mu * mu + 1e-5f);
        t1h[row * 512 + j]       = __float2half_rn(silu((x0 - mu) * inv * vg1[j] + vb1[j]));
        t1h[row * 512 + 256 + j] = __float2half_rn(silu((x1 - mu) * inv * vg1[j + 256] + vb1[j + 256]));
    }
}

// vW2 partials -> LN -> SiLU -> value head, one block per b
__global__ __launch_bounds__(256)
void vfin(const float* __restrict__ t0p, const float* __restrict__ g,
          const float* __restrict__ be, const float* __restrict__ Wh,
          const float* __restrict__ bh, float* __restrict__ out) {
    const size_t np = (size_t)BB * 512;
    int b = blockIdx.x, j = threadIdx.x;
    float x0 = t0p[(size_t)b * 512 + j]       + t0p[np + (size_t)b * 512 + j];
    float x1 = t0p[(size_t)b * 512 + 256 + j] + t0p[np + (size_t)b * 512 + 256 + j];
    float2 r = blockReduce2_256(make_float2(x0 + x1, x0 * x0 + x1 * x1));
    float mu = r.x * (1.f / 512.f);
    float inv = rsqrtf(r.y * (1.f / 512.f) - mu * mu + 1e-5f);
    float y0 = silu((x0 - mu) * inv * g[j] + be[j]);
    float y1 = silu((x1 - mu) * inv * g[j + 256] + be[j + 256]);
    float s = y0 * Wh[j] + y1 * Wh[256 + j];
    float2 r2 = blockReduce2_256(make_float2(s, 0.f));
    if (j == 0) out[b] = r2.x + bh[0];
}

// ---- fused LN + SiLU + diagonal q-head over q2pre (s-major rows) ----------
#define YSLD 520
__global__ __launch_bounds__(256)
void lnhead_q(const float* __restrict__ pre, const float* __restrict__ g,
              const float* __restrict__ be, const float* __restrict__ Wh,
              const float* __restrict__ bh, float* __restrict__ out) {
    extern __shared__ float sm[];
    float* whs = sm;             // [512][16]
    float* ys  = sm + 512 * 16;  // [64][YSLD]
    const int tid = threadIdx.x, lane = tid & 31, w = tid >> 5;
    const int r0 = blockIdx.x * 64;
    const int s16 = (r0 >> 11) * 16;

    for (int i = tid; i < 512 * 16; i += 256)
        whs[i] = Wh[(size_t)(i >> 4) * SBH + s16 + (i & 15)];

    for (int rr = w; rr < 64; rr += 8) {
        const float* row = pre + (size_t)(r0 + rr) * 512;
        float v[16];
        float s1 = 0.f, s2 = 0.f;
        #pragma unroll
        for (int i = 0; i < 16; i++) {
            v[i] = row[lane + i * 32];
            s1 += v[i]; s2 += v[i] * v[i];
        }
        #pragma unroll
        for (int o = 16; o > 0; o >>= 1) {
            s1 += __shfl_xor_sync(0xffffffffu, s1, o);
            s2 += __shfl_xor_sync(0xffffffffu, s2, o);
        }
        float mu = s1 * (1.f / 512.f);
        float inv = rsqrtf(s2 * (1.f / 512.f) - mu * mu + 1e-5f);
        #pragma unroll
        for (int i = 0; i < 16; i++) {
            int col = lane + i * 32;
            ys[rr * YSLD + col] = silu((v[i] - mu) * inv * g[col] + be[col]);
        }
    }
    __syncthreads();

    const int rid = tid >> 3, c2 = tid & 7;
    const float2 bias = *(const float2*)&bh[s16 + c2 * 2];
    float a0 = 0.f, a1 = 0.f, c0 = 0.f, c1 = 0.f;
    const float* y0r = ys + rid * YSLD;
    const float* y1r = ys + (rid + 32) * YSLD;
    #pragma unroll 8
    for (int k = 0; k < 512; k++) {
        float2 w2 = *(const float2*)&whs[k * 16 + c2 * 2];
        float ya = y0r[k], yb = y1r[k];
        a0 += ya * w2.x; a1 += ya * w2.y;
        c0 += yb * w2.x; c1 += yb * w2.y;
    }
    int brow0 = (r0 + rid) & (BB - 1);
    int brow1 = (r0 + rid + 32) & (BB - 1);
    *(float2*)&out[(size_t)brow0 * SBH + s16 + c2 * 2] = make_float2(a0 + bias.x, a1 + bias.y);
    *(float2*)&out[(size_t)brow1 * SBH + s16 + c2 * 2] = make_float2(c0 + bias.x, c1 + bias.y);
}

// ===================== launch ================================================
#define GEMM_DSMEM 49152
#define LNHEAD_DSMEM ((512 * 16 + 64 * YSLD) * 4)

extern "C" void kernel_launch(void* const* d_in, const int* in_sizes, int n_in,
                              void* d_out, int out_size) {
    const float* rgb_obs = (const float*)d_in[0];
    const float* low_obs = (const float*)d_in[1];
    const int*   category = (const int*)d_in[2];
    const float* v_W_rgb = (const float*)d_in[3];
    const float* v_g_rgb = (const float*)d_in[4];
    const float* v_b_rgb = (const float*)d_in[5];
    const float* v_W_low = (const float*)d_in[6];
    const float* v_g_low = (const float*)d_in[7];
    const float* v_b_low = (const float*)d_in[8];
    const float* v_W1 = (const float*)d_in[9];
    const float* v_g1 = (const float*)d_in[10];
    const float* v_b1 = (const float*)d_in[11];
    const float* v_W2 = (const float*)d_in[12];
    const float* v_g2 = (const float*)d_in[13];
    const float* v_b2 = (const float*)d_in[14];
    const float* v_Wh = (const float*)d_in[15];
    const float* v_bh = (const float*)d_in[16];
    const float* q_W_rgb = (const float*)d_in[17];
    const float* q_g_rgb = (const float*)d_in[18];
    const float* q_b_rgb = (const float*)d_in[19];
    const float* q_W_low = (const float*)d_in[20];
    const float* q_g_low = (const float*)d_in[21];
    const float* q_b_low = (const float*)d_in[22];
    const float* q_W1 = (const float*)d_in[23];
    const float* q_g1 = (const float*)d_in[24];
    const float* q_b1 = (const float*)d_in[25];
    const float* q_W2 = (const float*)d_in[26];
    const float* q_g2 = (const float*)d_in[27];
    const float* q_b2 = (const float*)d_in[28];
    const float* q_Wh = (const float*)d_in[29];
    const float* q_bh = (const float*)d_in[30];

    float* out_value = (float*)d_out;
    float* out_adv   = out_value + BB;

    cudaFuncSetAttribute(gemm_rgb,   cudaFuncAttributeMaxDynamicSharedMemorySize, GEMM_DSMEM);
    cudaFuncSetAttribute(gemm_dualA, cudaFuncAttributeMaxDynamicSharedMemorySize, GEMM_DSMEM);
    cudaFuncSetAttribute(gemm_dualB, cudaFuncAttributeMaxDynamicSharedMemorySize, GEMM_DSMEM);
    cudaFuncSetAttribute(lnhead_q,   cudaFuncAttributeMaxDynamicSharedMemorySize, LNHEAD_DSMEM);

    __half *Ahi, *WrgbTh, *WrgbTl, *xvh, *xqh;
    __half *vW1Th, *vW1Tl, *vW2Th, *vW2Tl, *qW1Th, *qW1Tl, *qW2Th, *qW2Tl;
    __half *t1h, *q1h;
    float *rgb_part, *act, *q2pre;
    cudaGetSymbolAddress((void**)&Ahi, g_Ahi);
    cudaGetSymbolAddress((void**)&WrgbTh, g_WrgbTh); cudaGetSymbolAddress((void**)&WrgbTl, g_WrgbTl);
    cudaGetSymbolAddress((void**)&rgb_part, g_rgb_part);
    cudaGetSymbolAddress((void**)&xvh, g_xvh);
    cudaGetSymbolAddress((void**)&xqh, g_xqh);
    cudaGetSymbolAddress((void**)&vW1Th, g_vW1Th); cudaGetSymbolAddress((void**)&vW1Tl, g_vW1Tl);
    cudaGetSymbolAddress((void**)&vW2Th, g_vW2Th); cudaGetSymbolAddress((void**)&vW2Tl, g_vW2Tl);
    cudaGetSymbolAddress((void**)&qW1Th, g_qW1Th); cudaGetSymbolAddress((void**)&qW1Tl, g_qW1Tl);
    cudaGetSymbolAddress((void**)&qW2Th, g_qW2Th); cudaGetSymbolAddress((void**)&qW2Tl, g_qW2Tl);
    cudaGetSymbolAddress((void**)&t1h, g_t1h);
    cudaGetSymbolAddress((void**)&act, g_act);
    cudaGetSymbolAddress((void**)&q1h, g_q1h);
    cudaGetSymbolAddress((void**)&q2pre, g_q2pre);

    float* t0p = rgb_part;                        // slices 0,1
    float* qbp = rgb_part + 2 * (size_t)BB * 512; // slices 2,3

    // ---- prep ----
    act_kernel<<<(BB * SS + 255) / 256, 256>>>(category, act);
    conv_hi<<<(BB * REPRK / 4 + 255) / 256, 256>>>(rgb_obs, Ahi, BB * REPRK / 4);
    trans_split_rgb<<<dim3(REPRK / 32, 512 / 32), dim3(32, 8)>>>(v_W_rgb, q_W_rgb, WrgbTh, WrgbTl);
    trans_split4<<<dim3(16, 16, 4), dim3(32, 8)>>>(v_W1, vW1Th, vW1Tl, v_W2, vW2Th, vW2Tl,
                                                   q_W1, qW1Th, qW1Tl, q_W2, qW2Th, qW2Tl);

    // ---- shared rgb features: split-K=4 over K=8192, reduce folded into LN ----
    gemm_rgb<<<dim3(4, BB / 128, 4), 512, GEMM_DSMEM>>>(Ahi, WrgbTh, WrgbTl, rgb_part);
    ln_tanh_rgb<<<dim3(BB, 2), 256>>>(rgb_part, v_g_rgb, v_b_rgb, q_g_rgb, q_b_rgb, xvh, xqh);
    low_kernel<<<BB, 256>>>(low_obs, v_W_low, v_g_low, v_b_low, q_W_low, q_g_low, q_b_low,
                            xvh, xqh);

    // ---- layer 1 (v + q packed, split-K=2 each) ----
    gemm_dualA<<<dim3(4, 16, 4), 512, GEMM_DSMEM>>>(xvh, vW1Th, vW1Tl,
                                                    xqh, qW1Th, qW1Tl, t0p, qbp);
    // ---- q1 expansion + v ln_silu in one launch ----
    mid_k<<<2 * BB, 256>>>(qbp, act, q_W1, q_g1, q_b1, t0p, v_g1, v_b1, q1h, t1h);

    // ---- layer 2: qW2 (big) + vW2 (splitk2) packed ----
    gemm_dualB<<<dim3(4, 416), 512, GEMM_DSMEM>>>(q1h, qW2Th, qW2Tl,
                                                  t1h, vW2Th, vW2Tl, q2pre, t0p);

    // ---- heads ----
    vfin<<<BB, 256>>>(t0p, v_g2, v_b2, v_Wh, v_bh, out_value);
    lnhead_q<<<(BB * SS) / 64, 256, LNHEAD_DSMEM>>>(q2pre, q_g2, q_b2, q_Wh, q_bh, out_adv);
}